// round 1
// baseline (speedup 1.0000x reference)
#include <cuda_runtime.h>
#include <math.h>

// ---------------- problem constants ----------------
#define Bb   8
#define Ls   512      // S == T == 512
#define Dm   512
#define Hh   8
#define DK_  64
#define DFF_ 2048
#define MROWS (Bb*Ls)   // 4096

// ---------------- scratch (device globals; no allocation) ----------------
__device__ float g_x   [Bb*Ls*Dm];
__device__ float g_y   [Bb*Ls*Dm];
__device__ float g_mem [Bb*Ls*Dm];
__device__ float g_q   [Bb*Hh*Ls*DK_];
__device__ float g_k   [Bb*Hh*Ls*DK_];
__device__ float g_v   [Bb*Hh*Ls*DK_];
__device__ float g_sc  [(size_t)Bb*Hh*Ls*Ls];
__device__ float g_ctx [Bb*Ls*Dm];
__device__ float g_tmp [Bb*Ls*Dm];
__device__ float g_h1  [(size_t)Bb*Ls*DFF_];

// ---------------- positional encoding add ----------------
__global__ void posenc_add(const float* __restrict__ in, float* __restrict__ out) {
    int idx = blockIdx.x * blockDim.x + threadIdx.x;
    if (idx >= Bb * Ls * Dm) return;
    int d = idx & (Dm - 1);
    int l = (idx >> 9) & (Ls - 1);
    int i2 = d & ~1;
    float div = expf(-(float)i2 * (9.210340371976184f / (float)Dm)); // ln(10000)/D
    float ang = (float)l * div;
    float pe = (d & 1) ? cosf(ang) : sinf(ang);
    out[idx] = in[idx] + pe;
}

// ---------------- generic SGEMM: C = A[MxK] * W[KxN] + bias ----------------
// mode 0: row-major write.  mode 1: head scatter [B,H,L,DK].
#define BM 128
#define BN 128
#define BK 16

__global__ void __launch_bounds__(256) gemm_kernel(
    const float* __restrict__ A, const float* __restrict__ W,
    const float* __restrict__ bias, float* __restrict__ C,
    int M, int N, int K, int mode, int relu)
{
    __shared__ float As[BK][BM];
    __shared__ float Bs[BK][BN];
    int tid = threadIdx.x;
    int bx = blockIdx.x, by = blockIdx.y;
    int tx = tid & 15, ty = tid >> 4;
    float acc[8][8];
#pragma unroll
    for (int i = 0; i < 8; i++)
#pragma unroll
        for (int j = 0; j < 8; j++) acc[i][j] = 0.f;

    const float* Ab = A + (size_t)by * BM * K;
    const float* Wb = W + (size_t)bx * BN;

    for (int k0 = 0; k0 < K; k0 += BK) {
        { // A tile: 128 rows x 16 k, stored transposed
            int r = tid >> 1;
            int c = (tid & 1) * 8;
            const float4* s = (const float4*)(Ab + (size_t)r * K + k0 + c);
            float4 v0 = s[0], v1 = s[1];
            As[c+0][r]=v0.x; As[c+1][r]=v0.y; As[c+2][r]=v0.z; As[c+3][r]=v0.w;
            As[c+4][r]=v1.x; As[c+5][r]=v1.y; As[c+6][r]=v1.z; As[c+7][r]=v1.w;
        }
        { // W tile: 16 k x 128 cols
            int r = tid >> 4;
            int c = (tid & 15) * 8;
            const float4* s = (const float4*)(Wb + (size_t)(k0 + r) * N + c);
            *(float4*)&Bs[r][c]   = s[0];
            *(float4*)&Bs[r][c+4] = s[1];
        }
        __syncthreads();
#pragma unroll
        for (int kk = 0; kk < BK; kk++) {
            float a[8], b[8];
#pragma unroll
            for (int i = 0; i < 8; i++) a[i] = As[kk][ty*8+i];
#pragma unroll
            for (int j = 0; j < 8; j++) b[j] = Bs[kk][tx*8+j];
#pragma unroll
            for (int i = 0; i < 8; i++)
#pragma unroll
                for (int j = 0; j < 8; j++) acc[i][j] += a[i] * b[j];
        }
        __syncthreads();
    }

#pragma unroll
    for (int i = 0; i < 8; i++) {
        int row = by * BM + ty * 8 + i;
#pragma unroll
        for (int j = 0; j < 8; j++) {
            int col = bx * BN + tx * 8 + j;
            float v = acc[i][j] + (bias ? bias[col] : 0.f);
            if (relu) v = fmaxf(v, 0.f);
            if (mode == 0) {
                C[(size_t)row * N + col] = v;
            } else {
                int b_ = row >> 9, l_ = row & (Ls - 1);
                int h_ = col >> 6, dk = col & (DK_ - 1);
                C[(((size_t)(b_ * Hh + h_)) * Ls + l_) * DK_ + dk] = v;
            }
        }
    }
}

// ---------------- scores = Q * K^T * 0.125 (per b,h) ----------------
// grid: (L/128 col tiles, L/128 row tiles, B*H)
#define SBK 32
__global__ void __launch_bounds__(256) scores_kernel(
    const float* __restrict__ Q, const float* __restrict__ Km,
    float* __restrict__ S, int causal)
{
    if (causal && (int)blockIdx.x > (int)blockIdx.y) return; // fully masked tile
    __shared__ float Qs[SBK][128];
    __shared__ float Ks[SBK][128];
    int bh = blockIdx.z;
    const float* Qb = Q + (size_t)bh * Ls * DK_ + (size_t)blockIdx.y * 128 * DK_;
    const float* Kb = Km + (size_t)bh * Ls * DK_ + (size_t)blockIdx.x * 128 * DK_;
    int tid = threadIdx.x;
    int tx = tid & 15, ty = tid >> 4;
    float acc[8][8];
#pragma unroll
    for (int i = 0; i < 8; i++)
#pragma unroll
        for (int j = 0; j < 8; j++) acc[i][j] = 0.f;

    for (int k0 = 0; k0 < DK_; k0 += SBK) {
        int r = tid >> 1;
        int c = (tid & 1) * 16;
        const float4* sq = (const float4*)(Qb + (size_t)r * DK_ + k0 + c);
        const float4* sk = (const float4*)(Kb + (size_t)r * DK_ + k0 + c);
#pragma unroll
        for (int q4 = 0; q4 < 4; q4++) {
            float4 v = sq[q4];
            Qs[c+q4*4+0][r]=v.x; Qs[c+q4*4+1][r]=v.y; Qs[c+q4*4+2][r]=v.z; Qs[c+q4*4+3][r]=v.w;
            float4 w = sk[q4];
            Ks[c+q4*4+0][r]=w.x; Ks[c+q4*4+1][r]=w.y; Ks[c+q4*4+2][r]=w.z; Ks[c+q4*4+3][r]=w.w;
        }
        __syncthreads();
#pragma unroll
        for (int kk = 0; kk < SBK; kk++) {
            float a[8], b[8];
#pragma unroll
            for (int i = 0; i < 8; i++) a[i] = Qs[kk][ty*8+i];
#pragma unroll
            for (int j = 0; j < 8; j++) b[j] = Ks[kk][tx*8+j];
#pragma unroll
            for (int i = 0; i < 8; i++)
#pragma unroll
                for (int j = 0; j < 8; j++) acc[i][j] += a[i] * b[j];
        }
        __syncthreads();
    }

    float* Sb = S + (size_t)bh * Ls * Ls;
#pragma unroll
    for (int i = 0; i < 8; i++) {
        int row = blockIdx.y * 128 + ty * 8 + i;
#pragma unroll
        for (int j = 0; j < 8; j++) {
            int col = blockIdx.x * 128 + tx * 8 + j;
            Sb[(size_t)row * Ls + col] = acc[i][j] * 0.125f;
        }
    }
}

// ---------------- softmax over rows of [BH*L, L], causal optional ----------------
__global__ void softmax_kernel(float* __restrict__ S, int causal) {
    __shared__ float red[256];
    size_t rowid = blockIdx.x;
    int q = (int)(rowid & (Ls - 1));
    float* row = S + rowid * Ls;
    int tid = threadIdx.x;
    int j0 = tid, j1 = tid + 256;
    float v0 = (causal && j0 > q) ? -1e9f : row[j0];
    float v1 = (causal && j1 > q) ? -1e9f : row[j1];
    red[tid] = fmaxf(v0, v1);
    __syncthreads();
    for (int s = 128; s > 0; s >>= 1) {
        if (tid < s) red[tid] = fmaxf(red[tid], red[tid + s]);
        __syncthreads();
    }
    float mx = red[0];
    __syncthreads();
    float e0 = __expf(v0 - mx), e1 = __expf(v1 - mx);
    red[tid] = e0 + e1;
    __syncthreads();
    for (int s = 128; s > 0; s >>= 1) {
        if (tid < s) red[tid] += red[tid + s];
        __syncthreads();
    }
    float inv = 1.f / red[0];
    row[j0] = e0 * inv;
    row[j1] = e1 * inv;
}

// ---------------- ctx = P * V  (per b,h), writes [B, L, H*DK] ----------------
// grid: (L/128 row tiles, B*H)
__global__ void __launch_bounds__(256) av_kernel(
    const float* __restrict__ P, const float* __restrict__ V,
    float* __restrict__ O, int causal)
{
    __shared__ float Ps[16][128];
    __shared__ float Vs[16][64];
    int bh = blockIdx.y;
    int b_ = bh >> 3, h_ = bh & 7;
    const float* Pb = P + (size_t)bh * Ls * Ls + (size_t)blockIdx.x * 128 * Ls;
    const float* Vb = V + (size_t)bh * Ls * DK_;
    int tid = threadIdx.x;
    int tx = tid & 15, ty = tid >> 4;
    float acc[8][4];
#pragma unroll
    for (int i = 0; i < 8; i++)
#pragma unroll
        for (int j = 0; j < 4; j++) acc[i][j] = 0.f;

    int kmax = causal ? (blockIdx.x + 1) * 128 : Ls;
    for (int k0 = 0; k0 < kmax; k0 += 16) {
        {
            int r = tid >> 1;
            int c = (tid & 1) * 8;
            const float4* s = (const float4*)(Pb + (size_t)r * Ls + k0 + c);
            float4 v0 = s[0], v1 = s[1];
            Ps[c+0][r]=v0.x; Ps[c+1][r]=v0.y; Ps[c+2][r]=v0.z; Ps[c+3][r]=v0.w;
            Ps[c+4][r]=v1.x; Ps[c+5][r]=v1.y; Ps[c+6][r]=v1.z; Ps[c+7][r]=v1.w;
        }
        {
            int r = tid >> 4;
            int c = (tid & 15) * 4;
            *(float4*)&Vs[r][c] = *(const float4*)(Vb + (size_t)(k0 + r) * DK_ + c);
        }
        __syncthreads();
#pragma unroll
        for (int kk = 0; kk < 16; kk++) {
            float a[8], b[4];
#pragma unroll
            for (int i = 0; i < 8; i++) a[i] = Ps[kk][ty*8+i];
#pragma unroll
            for (int j = 0; j < 4; j++) b[j] = Vs[kk][tx*4+j];
#pragma unroll
            for (int i = 0; i < 8; i++)
#pragma unroll
                for (int j = 0; j < 4; j++) acc[i][j] += a[i] * b[j];
        }
        __syncthreads();
    }

#pragma unroll
    for (int i = 0; i < 8; i++) {
        int l = blockIdx.x * 128 + ty * 8 + i;
#pragma unroll
        for (int j = 0; j < 4; j++) {
            O[((size_t)b_ * Ls + l) * Dm + h_ * DK_ + tx * 4 + j] = acc[i][j];
        }
    }
}

// ---------------- fused residual + LayerNorm (D=512, 256 threads) ----------------
__global__ void ln_kernel(const float* __restrict__ x, const float* __restrict__ res,
                          const float* __restrict__ g, const float* __restrict__ b,
                          float* __restrict__ out)
{
    __shared__ float r1[256];
    __shared__ float r2[256];
    size_t row = blockIdx.x;
    int tid = threadIdx.x;
    const float* xr = x + row * Dm;
    float v0 = xr[tid], v1 = xr[tid + 256];
    if (res) {
        const float* rr = res + row * Dm;
        v0 += rr[tid];
        v1 += rr[tid + 256];
    }
    r1[tid] = v0 + v1;
    r2[tid] = v0 * v0 + v1 * v1;
    __syncthreads();
    for (int s = 128; s > 0; s >>= 1) {
        if (tid < s) { r1[tid] += r1[tid + s]; r2[tid] += r2[tid + s]; }
        __syncthreads();
    }
    float mu = r1[0] * (1.f / Dm);
    float var = r2[0] * (1.f / Dm) - mu * mu;
    float rs = rsqrtf(var + 1e-5f);
    out[row * Dm + tid]       = (v0 - mu) * rs * g[tid]       + b[tid];
    out[row * Dm + tid + 256] = (v1 - mu) * rs * g[tid + 256] + b[tid + 256];
}

// ---------------- host orchestration ----------------
static inline void run_gemm(const float* A, const float* W, const float* bias,
                            float* C, int N, int K, int mode, int relu)
{
    dim3 grid(N / BN, MROWS / BM);
    gemm_kernel<<<grid, 256>>>(A, W, bias, C, MROWS, N, K, mode, relu);
}

extern "C" void kernel_launch(void* const* d_in, const int* in_sizes, int n_in,
                              void* d_out, int out_size)
{
    const float* src        = (const float*)d_in[0];
    const float* tgt        = (const float*)d_in[1];
    const float* enc_attn_W = (const float*)d_in[2];
    const float* enc_attn_b = (const float*)d_in[3];
    const float* enc_ffn_W1 = (const float*)d_in[4];
    const float* enc_ffn_b1 = (const float*)d_in[5];
    const float* enc_ffn_W2 = (const float*)d_in[6];
    const float* enc_ffn_b2 = (const float*)d_in[7];
    const float* enc_ln_g   = (const float*)d_in[8];
    const float* enc_ln_b   = (const float*)d_in[9];
    const float* enc_fng    = (const float*)d_in[10];
    const float* enc_fnb    = (const float*)d_in[11];
    const float* dec_sW     = (const float*)d_in[12];
    const float* dec_sb     = (const float*)d_in[13];
    const float* dec_cW     = (const float*)d_in[14];
    const float* dec_cb     = (const float*)d_in[15];
    const float* dW1        = (const float*)d_in[16];
    const float* db1        = (const float*)d_in[17];
    const float* dW2        = (const float*)d_in[18];
    const float* db2        = (const float*)d_in[19];
    const float* dec_ln_g   = (const float*)d_in[20];
    const float* dec_ln_b   = (const float*)d_in[21];
    const float* dec_fng    = (const float*)d_in[22];
    const float* dec_fnb    = (const float*)d_in[23];
    // d_in[24] = tgt_mask: exactly causal tril -> applied analytically.

    float *x, *y, *mem, *q, *k, *v, *sc, *ctx, *tmp, *h1;
    cudaGetSymbolAddress((void**)&x,   g_x);
    cudaGetSymbolAddress((void**)&y,   g_y);
    cudaGetSymbolAddress((void**)&mem, g_mem);
    cudaGetSymbolAddress((void**)&q,   g_q);
    cudaGetSymbolAddress((void**)&k,   g_k);
    cudaGetSymbolAddress((void**)&v,   g_v);
    cudaGetSymbolAddress((void**)&sc,  g_sc);
    cudaGetSymbolAddress((void**)&ctx, g_ctx);
    cudaGetSymbolAddress((void**)&tmp, g_tmp);
    cudaGetSymbolAddress((void**)&h1,  g_h1);

    const size_t DD = (size_t)Dm * Dm;
    const int nElem = Bb * Ls * Dm;

    // ===== encoder =====
    posenc_add<<<(nElem + 255) / 256, 256>>>(src, x);
    for (int l = 0; l < 4; l++) {
        const float* W  = enc_attn_W + (size_t)l * 4 * DD;
        const float* bb = enc_attn_b + (size_t)l * 4 * Dm;
        run_gemm(x, W,          bb,          q, Dm, Dm, 1, 0);
        run_gemm(x, W + DD,     bb + Dm,     k, Dm, Dm, 1, 0);
        run_gemm(x, W + 2 * DD, bb + 2 * Dm, v, Dm, Dm, 1, 0);
        scores_kernel<<<dim3(4, 4, Bb * Hh), 256>>>(q, k, sc, 0);
        softmax_kernel<<<Bb * Hh * Ls, 256>>>(sc, 0);
        av_kernel<<<dim3(4, Bb * Hh), 256>>>(sc, v, ctx, 0);
        run_gemm(ctx, W + 3 * DD, bb + 3 * Dm, tmp, Dm, Dm, 0, 0);
        ln_kernel<<<MROWS, 256>>>(x, tmp, enc_ln_g + (size_t)(l * 2) * Dm,
                                  enc_ln_b + (size_t)(l * 2) * Dm, x);
        run_gemm(x, enc_ffn_W1 + (size_t)l * Dm * DFF_, enc_ffn_b1 + (size_t)l * DFF_,
                 h1, DFF_, Dm, 0, 1);
        run_gemm(h1, enc_ffn_W2 + (size_t)l * DFF_ * Dm, enc_ffn_b2 + (size_t)l * Dm,
                 tmp, Dm, DFF_, 0, 0);
        ln_kernel<<<MROWS, 256>>>(x, tmp, enc_ln_g + (size_t)(l * 2 + 1) * Dm,
                                  enc_ln_b + (size_t)(l * 2 + 1) * Dm, x);
    }
    ln_kernel<<<MROWS, 256>>>(x, nullptr, enc_fng, enc_fnb, mem);

    // ===== decoder =====
    posenc_add<<<(nElem + 255) / 256, 256>>>(tgt, y);
    for (int l = 0; l < 4; l++) {
        // --- masked self-attention ---
        {
            const float* W  = dec_sW + (size_t)l * 4 * DD;
            const float* bb = dec_sb + (size_t)l * 4 * Dm;
            run_gemm(y, W,          bb,          q, Dm, Dm, 1, 0);
            run_gemm(y, W + DD,     bb + Dm,     k, Dm, Dm, 1, 0);
            run_gemm(y, W + 2 * DD, bb + 2 * Dm, v, Dm, Dm, 1, 0);
            scores_kernel<<<dim3(4, 4, Bb * Hh), 256>>>(q, k, sc, 1);
            softmax_kernel<<<Bb * Hh * Ls, 256>>>(sc, 1);
            av_kernel<<<dim3(4, Bb * Hh), 256>>>(sc, v, ctx, 1);
            run_gemm(ctx, W + 3 * DD, bb + 3 * Dm, tmp, Dm, Dm, 0, 0);
            ln_kernel<<<MROWS, 256>>>(y, tmp, dec_ln_g + (size_t)(l * 3) * Dm,
                                      dec_ln_b + (size_t)(l * 3) * Dm, y);
        }
        // --- cross-attention ---
        {
            const float* W  = dec_cW + (size_t)l * 4 * DD;
            const float* bb = dec_cb + (size_t)l * 4 * Dm;
            run_gemm(y,   W,          bb,          q, Dm, Dm, 1, 0);
            run_gemm(mem, W + DD,     bb + Dm,     k, Dm, Dm, 1, 0);
            run_gemm(mem, W + 2 * DD, bb + 2 * Dm, v, Dm, Dm, 1, 0);
            scores_kernel<<<dim3(4, 4, Bb * Hh), 256>>>(q, k, sc, 0);
            softmax_kernel<<<Bb * Hh * Ls, 256>>>(sc, 0);
            av_kernel<<<dim3(4, Bb * Hh), 256>>>(sc, v, ctx, 0);
            run_gemm(ctx, W + 3 * DD, bb + 3 * Dm, tmp, Dm, Dm, 0, 0);
            ln_kernel<<<MROWS, 256>>>(y, tmp, dec_ln_g + (size_t)(l * 3 + 1) * Dm,
                                      dec_ln_b + (size_t)(l * 3 + 1) * Dm, y);
        }
        // --- FFN ---
        run_gemm(y, dW1 + (size_t)l * Dm * DFF_, db1 + (size_t)l * DFF_, h1, DFF_, Dm, 0, 1);
        run_gemm(h1, dW2 + (size_t)l * DFF_ * Dm, db2 + (size_t)l * Dm, tmp, Dm, DFF_, 0, 0);
        ln_kernel<<<MROWS, 256>>>(y, tmp, dec_ln_g + (size_t)(l * 3 + 2) * Dm,
                                  dec_ln_b + (size_t)(l * 3 + 2) * Dm, y);
    }
    ln_kernel<<<MROWS, 256>>>(y, nullptr, dec_fng, dec_fnb, (float*)d_out);
}

// round 3
// speedup vs baseline: 1.8863x; 1.8863x over previous
#include <cuda_runtime.h>
#include <cuda_bf16.h>
#include <cstdint>
#include <math.h>

// ---------------- problem constants ----------------
#define Bb   8
#define Ls   512
#define Dm   512
#define Hh   8
#define DK_  64
#define DFF_ 2048
#define MROWS (Bb*Ls)   // 4096

// ---------------- scratch (device globals; no allocation) ----------------
__device__ float g_x   [Bb*Ls*Dm];
__device__ float g_y   [Bb*Ls*Dm];
__device__ float g_mem [Bb*Ls*Dm];
__device__ float g_q   [Bb*Hh*Ls*DK_];
__device__ float g_k   [Bb*Hh*Ls*DK_];
__device__ float g_v   [Bb*Hh*Ls*DK_];
__device__ float g_sc  [(size_t)Bb*Hh*Ls*Ls];
__device__ float g_ctx [Bb*Ls*Dm];
__device__ float g_tmp [Bb*Ls*Dm];
__device__ float g_h1  [(size_t)Bb*Ls*DFF_];

// ================= mma.sync helpers (sm_80-class; valid on sm_103) =========
__device__ __forceinline__ uint32_t smem_u32(const void* p) {
    uint32_t a;
    asm("{ .reg .u64 t; cvta.to.shared.u64 t, %1; cvt.u32.u64 %0, t; }" : "=r"(a) : "l"(p));
    return a;
}
__device__ __forceinline__ void ldmA(uint32_t* f, uint32_t addr) {
    asm volatile("ldmatrix.sync.aligned.m8n8.x4.shared.b16 {%0,%1,%2,%3}, [%4];"
                 : "=r"(f[0]), "=r"(f[1]), "=r"(f[2]), "=r"(f[3]) : "r"(addr));
}
__device__ __forceinline__ void ldmBT(uint32_t* f, uint32_t addr) {
    asm volatile("ldmatrix.sync.aligned.m8n8.x4.trans.shared.b16 {%0,%1,%2,%3}, [%4];"
                 : "=r"(f[0]), "=r"(f[1]), "=r"(f[2]), "=r"(f[3]) : "r"(addr));
}
__device__ __forceinline__ void mma16816(float* c, const uint32_t* a, const uint32_t* b) {
    asm volatile("mma.sync.aligned.m16n8k16.row.col.f32.bf16.bf16.f32 "
                 "{%0,%1,%2,%3}, {%4,%5,%6,%7}, {%8,%9}, {%0,%1,%2,%3};"
                 : "+f"(c[0]), "+f"(c[1]), "+f"(c[2]), "+f"(c[3])
                 : "r"(a[0]), "r"(a[1]), "r"(a[2]), "r"(a[3]), "r"(b[0]), "r"(b[1]));
}
__device__ __forceinline__ uint32_t pack_split(float x0, float x1, uint32_t& lo_out) {
    __nv_bfloat16 h0 = __float2bfloat16(x0);
    __nv_bfloat16 h1 = __float2bfloat16(x1);
    __nv_bfloat16 l0 = __float2bfloat16(x0 - __bfloat162float(h0));
    __nv_bfloat16 l1 = __float2bfloat16(x1 - __bfloat162float(h1));
    __nv_bfloat162 hp = {h0, h1}, lp = {l0, l1};
    lo_out = *(uint32_t*)&lp;
    return *(uint32_t*)&hp;
}

// smem layout (bytes), per stage
#define APITCH 40     // bf16 elements per A row (32 + 8 pad)
#define BPITCH 136    // bf16 elements per B row (128 + 8 pad)
#define OFF_A_HI 0
#define OFF_A_LO (128*APITCH*2)                 // 10240
#define OFF_B_HI (2*128*APITCH*2)               // 20480
#define OFF_B_LO (2*128*APITCH*2 + 32*BPITCH*2) // 29184
#define STAGE_SZ (2*128*APITCH*2 + 2*32*BPITCH*2)  // 37888
#define GM_SMEM  (2*STAGE_SZ)                   // 75776

// ================ bf16x3 split-precision tensor-core GEMM ==================
// C[4096, Nmat] = A[4096, K] * W[K, Nmat] + bias, per 128x128 tile.
// blockIdx.x spans nTilesX tiles across (possibly several) weight matrices of
// width Nmat separated by Wstride. mode 0: row-major into C0. mode 1: head
// scatter [B,H,L,DK] into C{0,1,2} selected by matrix index.
__global__ void __launch_bounds__(256, 1) gemm_mma(
    const float* __restrict__ A, const float* __restrict__ W,
    const float* __restrict__ bias,
    float* __restrict__ C0, float* __restrict__ C1, float* __restrict__ C2,
    int K, int Nmat, long long Wstride, int mode, int relu)
{
    extern __shared__ char smem[];
    const uint32_t sb = smem_u32(smem);
    const int tid = threadIdx.x;
    const int wid = tid >> 5, lid = tid & 31;
    const int wm = wid & 3, wn = wid >> 2;        // 4 x 2 warp grid
    const int m0 = wm * 32, n0 = wn * 64;

    const int nbase = blockIdx.x * 128;
    const int mat = nbase / Nmat;
    const int ncol = nbase - mat * Nmat;
    const float* Wp = W + (size_t)mat * (size_t)Wstride + ncol;
    const float* Ap = A + (size_t)blockIdx.y * 128 * (size_t)K;

    float acc[2][8][4];
#pragma unroll
    for (int i = 0; i < 2; i++)
#pragma unroll
        for (int j = 0; j < 8; j++)
#pragma unroll
            for (int r = 0; r < 4; r++) acc[i][j][r] = 0.f;

    // per-thread gmem slots
    const int arow = tid >> 3, ac4 = tid & 7;       // A: 4 rows apart per i
    const int brow = tid >> 5, bc4 = tid & 31;      // B: 8 rows apart per i

    float4 aR[4], bR[4];
    auto loadG = [&](int t) {
        const int k0 = t * 32;
#pragma unroll
        for (int i = 0; i < 4; i++)
            aR[i] = *(const float4*)(Ap + (size_t)(arow + i * 32) * K + k0 + ac4 * 4);
#pragma unroll
        for (int i = 0; i < 4; i++)
            bR[i] = *(const float4*)(Wp + (size_t)(k0 + brow + i * 8) * Nmat + bc4 * 4);
    };
    auto storeS = [&](int s) {
        char* base = smem + s * STAGE_SZ;
#pragma unroll
        for (int i = 0; i < 4; i++) {
            uint32_t l0, l1, h0, h1;
            h0 = pack_split(aR[i].x, aR[i].y, l0);
            h1 = pack_split(aR[i].z, aR[i].w, l1);
            uint32_t off = ((arow + i * 32) * APITCH + ac4 * 4) * 2;
            *(uint2*)(base + OFF_A_HI + off) = make_uint2(h0, h1);
            *(uint2*)(base + OFF_A_LO + off) = make_uint2(l0, l1);
        }
#pragma unroll
        for (int i = 0; i < 4; i++) {
            uint32_t l0, l1, h0, h1;
            h0 = pack_split(bR[i].x, bR[i].y, l0);
            h1 = pack_split(bR[i].z, bR[i].w, l1);
            uint32_t off = ((brow + i * 8) * BPITCH + bc4 * 4) * 2;
            *(uint2*)(base + OFF_B_HI + off) = make_uint2(h0, h1);
            *(uint2*)(base + OFF_B_LO + off) = make_uint2(l0, l1);
        }
    };

    // lane-derived ldmatrix row/col
    const int lr = (lid & 7) + ((lid >> 3) & 1) * 8;
    const int lc = (lid >> 4) * 8;

    loadG(0);
    storeS(0);
    __syncthreads();

    const int T = K / 32;
    for (int t = 0; t < T; t++) {
        if (t + 1 < T) loadG(t + 1);
        const uint32_t stg = sb + (t & 1) * STAGE_SZ;
#pragma unroll
        for (int ks = 0; ks < 2; ks++) {
            uint32_t ah[2][4], al[2][4];
#pragma unroll
            for (int mt = 0; mt < 2; mt++) {
                uint32_t aoff = ((m0 + mt * 16 + lr) * APITCH + ks * 16 + lc) * 2;
                ldmA(ah[mt], stg + OFF_A_HI + aoff);
                ldmA(al[mt], stg + OFF_A_LO + aoff);
            }
            uint32_t bh[4][4], bl[4][4];
#pragma unroll
            for (int ng = 0; ng < 4; ng++) {
                uint32_t boff = ((ks * 16 + lr) * BPITCH + n0 + ng * 16 + lc) * 2;
                ldmBT(bh[ng], stg + OFF_B_HI + boff);
                ldmBT(bl[ng], stg + OFF_B_LO + boff);
            }
#pragma unroll
            for (int mt = 0; mt < 2; mt++)
#pragma unroll
                for (int j = 0; j < 8; j++) {
                    const uint32_t* bph = &bh[j >> 1][(j & 1) * 2];
                    const uint32_t* bpl = &bl[j >> 1][(j & 1) * 2];
                    mma16816(acc[mt][j], ah[mt], bph);
                    mma16816(acc[mt][j], ah[mt], bpl);
                    mma16816(acc[mt][j], al[mt], bph);
                }
        }
        if (t + 1 < T) {
            storeS((t + 1) & 1);
            __syncthreads();
        }
    }

    // ---- epilogue ----
    const int g = lid >> 2, tq = lid & 3;
    const int browBase = blockIdx.y * 128 + m0;
#pragma unroll
    for (int mt = 0; mt < 2; mt++) {
#pragma unroll
        for (int j = 0; j < 8; j++) {
            int col = ncol + n0 + j * 8 + tq * 2;
            float b0 = bias[(size_t)mat * Nmat + col];
            float b1 = bias[(size_t)mat * Nmat + col + 1];
#pragma unroll
            for (int h = 0; h < 2; h++) {
                int row = browBase + mt * 16 + g + h * 8;
                float v0 = acc[mt][j][h * 2 + 0] + b0;
                float v1 = acc[mt][j][h * 2 + 1] + b1;
                if (relu) { v0 = fmaxf(v0, 0.f); v1 = fmaxf(v1, 0.f); }
                if (mode == 0) {
                    *(float2*)(C0 + (size_t)row * Nmat + col) = make_float2(v0, v1);
                } else {
                    float* C = (mat == 0) ? C0 : ((mat == 1) ? C1 : C2);
                    int b_ = row >> 9, l_ = row & (Ls - 1);
                    int h_ = col >> 6, dk = col & (DK_ - 1);
                    *(float2*)(C + (((size_t)(b_ * Hh + h_)) * Ls + l_) * DK_ + dk)
                        = make_float2(v0, v1);
                }
            }
        }
    }
}

// ---------------- positional encoding add ----------------
__global__ void posenc_add(const float* __restrict__ in, float* __restrict__ out) {
    int idx = blockIdx.x * blockDim.x + threadIdx.x;
    if (idx >= Bb * Ls * Dm) return;
    int d = idx & (Dm - 1);
    int l = (idx >> 9) & (Ls - 1);
    int i2 = d & ~1;
    float div = expf(-(float)i2 * (9.210340371976184f / (float)Dm));
    float ang = (float)l * div;
    float pe = (d & 1) ? cosf(ang) : sinf(ang);
    out[idx] = in[idx] + pe;
}

// ---------------- scores = Q * K^T * 0.125 (per b,h) ----------------
#define SBK 32
__global__ void __launch_bounds__(256) scores_kernel(
    const float* __restrict__ Q, const float* __restrict__ Km,
    float* __restrict__ S, int causal)
{
    if (causal && (int)blockIdx.x > (int)blockIdx.y) return;
    __shared__ float Qs[SBK][128];
    __shared__ float Ks[SBK][128];
    int bh = blockIdx.z;
    const float* Qb = Q + (size_t)bh * Ls * DK_ + (size_t)blockIdx.y * 128 * DK_;
    const float* Kb = Km + (size_t)bh * Ls * DK_ + (size_t)blockIdx.x * 128 * DK_;
    int tid = threadIdx.x;
    int tx = tid & 15, ty = tid >> 4;
    float acc[8][8];
#pragma unroll
    for (int i = 0; i < 8; i++)
#pragma unroll
        for (int j = 0; j < 8; j++) acc[i][j] = 0.f;

    for (int k0 = 0; k0 < DK_; k0 += SBK) {
        int r = tid >> 1;
        int c = (tid & 1) * 16;
        const float4* sq = (const float4*)(Qb + (size_t)r * DK_ + k0 + c);
        const float4* sk = (const float4*)(Kb + (size_t)r * DK_ + k0 + c);
#pragma unroll
        for (int q4 = 0; q4 < 4; q4++) {
            float4 v = sq[q4];
            Qs[c+q4*4+0][r]=v.x; Qs[c+q4*4+1][r]=v.y; Qs[c+q4*4+2][r]=v.z; Qs[c+q4*4+3][r]=v.w;
            float4 w = sk[q4];
            Ks[c+q4*4+0][r]=w.x; Ks[c+q4*4+1][r]=w.y; Ks[c+q4*4+2][r]=w.z; Ks[c+q4*4+3][r]=w.w;
        }
        __syncthreads();
#pragma unroll
        for (int kk = 0; kk < SBK; kk++) {
            float a[8], b[8];
#pragma unroll
            for (int i = 0; i < 8; i++) a[i] = Qs[kk][ty*8+i];
#pragma unroll
            for (int j = 0; j < 8; j++) b[j] = Ks[kk][tx*8+j];
#pragma unroll
            for (int i = 0; i < 8; i++)
#pragma unroll
                for (int j = 0; j < 8; j++) acc[i][j] += a[i] * b[j];
        }
        __syncthreads();
    }

    float* Sb = S + (size_t)bh * Ls * Ls;
#pragma unroll
    for (int i = 0; i < 8; i++) {
        int row = blockIdx.y * 128 + ty * 8 + i;
#pragma unroll
        for (int j = 0; j < 8; j++) {
            int col = blockIdx.x * 128 + tx * 8 + j;
            Sb[(size_t)row * Ls + col] = acc[i][j] * 0.125f;
        }
    }
}

// ---------------- softmax ----------------
__global__ void softmax_kernel(float* __restrict__ S, int causal) {
    __shared__ float red[256];
    size_t rowid = blockIdx.x;
    int q = (int)(rowid & (Ls - 1));
    float* row = S + rowid * Ls;
    int tid = threadIdx.x;
    int j0 = tid, j1 = tid + 256;
    float v0 = (causal && j0 > q) ? -1e9f : row[j0];
    float v1 = (causal && j1 > q) ? -1e9f : row[j1];
    red[tid] = fmaxf(v0, v1);
    __syncthreads();
    for (int s = 128; s > 0; s >>= 1) {
        if (tid < s) red[tid] = fmaxf(red[tid], red[tid + s]);
        __syncthreads();
    }
    float mx = red[0];
    __syncthreads();
    float e0 = __expf(v0 - mx), e1 = __expf(v1 - mx);
    red[tid] = e0 + e1;
    __syncthreads();
    for (int s = 128; s > 0; s >>= 1) {
        if (tid < s) red[tid] += red[tid + s];
        __syncthreads();
    }
    float inv = 1.f / red[0];
    row[j0] = e0 * inv;
    row[j1] = e1 * inv;
}

// ---------------- ctx = P * V ----------------
__global__ void __launch_bounds__(256) av_kernel(
    const float* __restrict__ P, const float* __restrict__ V,
    float* __restrict__ O, int causal)
{
    __shared__ float Ps[16][128];
    __shared__ float Vs[16][64];
    int bh = blockIdx.y;
    int b_ = bh >> 3, h_ = bh & 7;
    const float* Pb = P + (size_t)bh * Ls * Ls + (size_t)blockIdx.x * 128 * Ls;
    const float* Vb = V + (size_t)bh * Ls * DK_;
    int tid = threadIdx.x;
    int tx = tid & 15, ty = tid >> 4;
    float acc[8][4];
#pragma unroll
    for (int i = 0; i < 8; i++)
#pragma unroll
        for (int j = 0; j < 4; j++) acc[i][j] = 0.f;

    int kmax = causal ? (blockIdx.x + 1) * 128 : Ls;
    for (int k0 = 0; k0 < kmax; k0 += 16) {
        {
            int r = tid >> 1;
            int c = (tid & 1) * 8;
            const float4* s = (const float4*)(Pb + (size_t)r * Ls + k0 + c);
            float4 v0 = s[0], v1 = s[1];
            Ps[c+0][r]=v0.x; Ps[c+1][r]=v0.y; Ps[c+2][r]=v0.z; Ps[c+3][r]=v0.w;
            Ps[c+4][r]=v1.x; Ps[c+5][r]=v1.y; Ps[c+6][r]=v1.z; Ps[c+7][r]=v1.w;
        }
        {
            int r = tid >> 4;
            int c = (tid & 15) * 4;
            *(float4*)&Vs[r][c] = *(const float4*)(Vb + (size_t)(k0 + r) * DK_ + c);
        }
        __syncthreads();
#pragma unroll
        for (int kk = 0; kk < 16; kk++) {
            float a[8], b[4];
#pragma unroll
            for (int i = 0; i < 8; i++) a[i] = Ps[kk][ty*8+i];
#pragma unroll
            for (int j = 0; j < 4; j++) b[j] = Vs[kk][tx*4+j];
#pragma unroll
            for (int i = 0; i < 8; i++)
#pragma unroll
                for (int j = 0; j < 4; j++) acc[i][j] += a[i] * b[j];
        }
        __syncthreads();
    }

#pragma unroll
    for (int i = 0; i < 8; i++) {
        int l = blockIdx.x * 128 + ty * 8 + i;
#pragma unroll
        for (int j = 0; j < 4; j++) {
            O[((size_t)b_ * Ls + l) * Dm + h_ * DK_ + tx * 4 + j] = acc[i][j];
        }
    }
}

// ---------------- fused residual + LayerNorm ----------------
__global__ void ln_kernel(const float* __restrict__ x, const float* __restrict__ res,
                          const float* __restrict__ g, const float* __restrict__ b,
                          float* __restrict__ out)
{
    __shared__ float r1[256];
    __shared__ float r2[256];
    size_t row = blockIdx.x;
    int tid = threadIdx.x;
    const float* xr = x + row * Dm;
    float v0 = xr[tid], v1 = xr[tid + 256];
    if (res) {
        const float* rr = res + row * Dm;
        v0 += rr[tid];
        v1 += rr[tid + 256];
    }
    r1[tid] = v0 + v1;
    r2[tid] = v0 * v0 + v1 * v1;
    __syncthreads();
    for (int s = 128; s > 0; s >>= 1) {
        if (tid < s) { r1[tid] += r1[tid + s]; r2[tid] += r2[tid + s]; }
        __syncthreads();
    }
    float mu = r1[0] * (1.f / Dm);
    float var = r2[0] * (1.f / Dm) - mu * mu;
    float rs = rsqrtf(var + 1e-5f);
    out[row * Dm + tid]       = (v0 - mu) * rs * g[tid]       + b[tid];
    out[row * Dm + tid + 256] = (v1 - mu) * rs * g[tid + 256] + b[tid + 256];
}

// ---------------- host orchestration ----------------
static inline void run_mma(const float* A, const float* W, const float* bias,
                           float* C0, float* C1, float* C2,
                           int K, int Nmat, long long Wstride, int nTilesX,
                           int mode, int relu)
{
    static bool attrSet = false;
    if (!attrSet) {
        cudaFuncSetAttribute(gemm_mma, cudaFuncAttributeMaxDynamicSharedMemorySize, GM_SMEM);
        attrSet = true;
    }
    dim3 grid(nTilesX, MROWS / 128);
    gemm_mma<<<grid, 256, GM_SMEM>>>(A, W, bias, C0, C1, C2, K, Nmat, Wstride, mode, relu);
}

extern "C" void kernel_launch(void* const* d_in, const int* in_sizes, int n_in,
                              void* d_out, int out_size)
{
    const float* src        = (const float*)d_in[0];
    const float* tgt        = (const float*)d_in[1];
    const float* enc_attn_W = (const float*)d_in[2];
    const float* enc_attn_b = (const float*)d_in[3];
    const float* enc_ffn_W1 = (const float*)d_in[4];
    const float* enc_ffn_b1 = (const float*)d_in[5];
    const float* enc_ffn_W2 = (const float*)d_in[6];
    const float* enc_ffn_b2 = (const float*)d_in[7];
    const float* enc_ln_g   = (const float*)d_in[8];
    const float* enc_ln_b   = (const float*)d_in[9];
    const float* enc_fng    = (const float*)d_in[10];
    const float* enc_fnb    = (const float*)d_in[11];
    const float* dec_sW     = (const float*)d_in[12];
    const float* dec_sb     = (const float*)d_in[13];
    const float* dec_cW     = (const float*)d_in[14];
    const float* dec_cb     = (const float*)d_in[15];
    const float* dW1        = (const float*)d_in[16];
    const float* db1        = (const float*)d_in[17];
    const float* dW2        = (const float*)d_in[18];
    const float* db2        = (const float*)d_in[19];
    const float* dec_ln_g   = (const float*)d_in[20];
    const float* dec_ln_b   = (const float*)d_in[21];
    const float* dec_fng    = (const float*)d_in[22];
    const float* dec_fnb    = (const float*)d_in[23];
    // d_in[24] = tgt_mask: exact causal tril -> applied analytically.

    float *x, *y, *mem, *q, *k, *v, *sc, *ctx, *tmp, *h1;
    cudaGetSymbolAddress((void**)&x,   g_x);
    cudaGetSymbolAddress((void**)&y,   g_y);
    cudaGetSymbolAddress((void**)&mem, g_mem);
    cudaGetSymbolAddress((void**)&q,   g_q);
    cudaGetSymbolAddress((void**)&k,   g_k);
    cudaGetSymbolAddress((void**)&v,   g_v);
    cudaGetSymbolAddress((void**)&sc,  g_sc);
    cudaGetSymbolAddress((void**)&ctx, g_ctx);
    cudaGetSymbolAddress((void**)&tmp, g_tmp);
    cudaGetSymbolAddress((void**)&h1,  g_h1);

    const long long DD = (long long)Dm * Dm;
    const int nElem = Bb * Ls * Dm;

    // ===== encoder =====
    posenc_add<<<(nElem + 255) / 256, 256>>>(src, x);
    for (int l = 0; l < 4; l++) {
        const float* W  = enc_attn_W + (size_t)l * 4 * DD;
        const float* bb = enc_attn_b + (size_t)l * 4 * Dm;
        run_mma(x, W, bb, q, k, v, Dm, Dm, DD, 12, 1, 0);          // fused QKV
        scores_kernel<<<dim3(4, 4, Bb * Hh), 256>>>(q, k, sc, 0);
        softmax_kernel<<<Bb * Hh * Ls, 256>>>(sc, 0);
        av_kernel<<<dim3(4, Bb * Hh), 256>>>(sc, v, ctx, 0);
        run_mma(ctx, W + 3 * DD, bb + 3 * Dm, tmp, 0, 0, Dm, Dm, 0, 4, 0, 0);
        ln_kernel<<<MROWS, 256>>>(x, tmp, enc_ln_g + (size_t)(l * 2) * Dm,
                                  enc_ln_b + (size_t)(l * 2) * Dm, x);
        run_mma(x, enc_ffn_W1 + (size_t)l * Dm * DFF_, enc_ffn_b1 + (size_t)l * DFF_,
                h1, 0, 0, Dm, DFF_, 0, 16, 0, 1);
        run_mma(h1, enc_ffn_W2 + (size_t)l * DFF_ * Dm, enc_ffn_b2 + (size_t)l * Dm,
                tmp, 0, 0, DFF_, Dm, 0, 4, 0, 0);
        ln_kernel<<<MROWS, 256>>>(x, tmp, enc_ln_g + (size_t)(l * 2 + 1) * Dm,
                                  enc_ln_b + (size_t)(l * 2 + 1) * Dm, x);
    }
    ln_kernel<<<MROWS, 256>>>(x, nullptr, enc_fng, enc_fnb, mem);

    // ===== decoder =====
    posenc_add<<<(nElem + 255) / 256, 256>>>(tgt, y);
    for (int l = 0; l < 4; l++) {
        // masked self-attention
        {
            const float* W  = dec_sW + (size_t)l * 4 * DD;
            const float* bb = dec_sb + (size_t)l * 4 * Dm;
            run_mma(y, W, bb, q, k, v, Dm, Dm, DD, 12, 1, 0);
            scores_kernel<<<dim3(4, 4, Bb * Hh), 256>>>(q, k, sc, 1);
            softmax_kernel<<<Bb * Hh * Ls, 256>>>(sc, 1);
            av_kernel<<<dim3(4, Bb * Hh), 256>>>(sc, v, ctx, 1);
            run_mma(ctx, W + 3 * DD, bb + 3 * Dm, tmp, 0, 0, Dm, Dm, 0, 4, 0, 0);
            ln_kernel<<<MROWS, 256>>>(y, tmp, dec_ln_g + (size_t)(l * 3) * Dm,
                                      dec_ln_b + (size_t)(l * 3) * Dm, y);
        }
        // cross-attention
        {
            const float* W  = dec_cW + (size_t)l * 4 * DD;
            const float* bb = dec_cb + (size_t)l * 4 * Dm;
            run_mma(y,   W,      bb,      q, 0, 0, Dm, Dm, 0, 4, 1, 0);      // Q from y
            run_mma(mem, W + DD, bb + Dm, k, v, 0, Dm, Dm, DD, 8, 1, 0);     // fused K,V
            scores_kernel<<<dim3(4, 4, Bb * Hh), 256>>>(q, k, sc, 0);
            softmax_kernel<<<Bb * Hh * Ls, 256>>>(sc, 0);
            av_kernel<<<dim3(4, Bb * Hh), 256>>>(sc, v, ctx, 0);
            run_mma(ctx, W + 3 * DD, bb + 3 * Dm, tmp, 0, 0, Dm, Dm, 0, 4, 0, 0);
            ln_kernel<<<MROWS, 256>>>(y, tmp, dec_ln_g + (size_t)(l * 3 + 1) * Dm,
                                      dec_ln_b + (size_t)(l * 3 + 1) * Dm, y);
        }
        // FFN
        run_mma(y, dW1 + (size_t)l * Dm * DFF_, db1 + (size_t)l * DFF_,
                h1, 0, 0, Dm, DFF_, 0, 16, 0, 1);
        run_mma(h1, dW2 + (size_t)l * DFF_ * Dm, db2 + (size_t)l * Dm,
                tmp, 0, 0, DFF_, Dm, 0, 4, 0, 0);
        ln_kernel<<<MROWS, 256>>>(y, tmp, dec_ln_g + (size_t)(l * 3 + 2) * Dm,
                                  dec_ln_b + (size_t)(l * 3 + 2) * Dm, y);
    }
    ln_kernel<<<MROWS, 256>>>(y, nullptr, dec_fng, dec_fnb, (float*)d_out);
}

// round 4
// speedup vs baseline: 2.9385x; 1.5578x over previous
#include <cuda_runtime.h>
#include <cuda_bf16.h>
#include <cstdint>
#include <math.h>

// ---------------- problem constants ----------------
#define Bb   8
#define Ls   512
#define Dm   512
#define Hh   8
#define DK_  64
#define DFF_ 2048
#define MROWS (Bb*Ls)   // 4096

// ---------------- scratch (device globals; no allocation) ----------------
__device__ float g_x   [Bb*Ls*Dm];
__device__ float g_y   [Bb*Ls*Dm];
__device__ float g_mem [Bb*Ls*Dm];
__device__ float g_q   [Bb*Hh*Ls*DK_];
__device__ float g_k   [Bb*Hh*Ls*DK_];
__device__ float g_v   [Bb*Hh*Ls*DK_];
__device__ float g_ctx [Bb*Ls*Dm];
__device__ float g_tmp [Bb*Ls*Dm];
__device__ float g_h1  [(size_t)Bb*Ls*DFF_];

// ================= mma.sync helpers (sm_80-class; valid on sm_103) =========
__device__ __forceinline__ uint32_t smem_u32(const void* p) {
    uint32_t a;
    asm("{ .reg .u64 t; cvta.to.shared.u64 t, %1; cvt.u32.u64 %0, t; }" : "=r"(a) : "l"(p));
    return a;
}
__device__ __forceinline__ void ldmA(uint32_t* f, uint32_t addr) {
    asm volatile("ldmatrix.sync.aligned.m8n8.x4.shared.b16 {%0,%1,%2,%3}, [%4];"
                 : "=r"(f[0]), "=r"(f[1]), "=r"(f[2]), "=r"(f[3]) : "r"(addr));
}
__device__ __forceinline__ void ldmBT(uint32_t* f, uint32_t addr) {
    asm volatile("ldmatrix.sync.aligned.m8n8.x4.trans.shared.b16 {%0,%1,%2,%3}, [%4];"
                 : "=r"(f[0]), "=r"(f[1]), "=r"(f[2]), "=r"(f[3]) : "r"(addr));
}
__device__ __forceinline__ void mma16816(float* c, const uint32_t* a, const uint32_t* b) {
    asm volatile("mma.sync.aligned.m16n8k16.row.col.f32.bf16.bf16.f32 "
                 "{%0,%1,%2,%3}, {%4,%5,%6,%7}, {%8,%9}, {%0,%1,%2,%3};"
                 : "+f"(c[0]), "+f"(c[1]), "+f"(c[2]), "+f"(c[3])
                 : "r"(a[0]), "r"(a[1]), "r"(a[2]), "r"(a[3]), "r"(b[0]), "r"(b[1]));
}
__device__ __forceinline__ uint32_t pack_split(float x0, float x1, uint32_t& lo_out) {
    __nv_bfloat16 h0 = __float2bfloat16(x0);
    __nv_bfloat16 h1 = __float2bfloat16(x1);
    __nv_bfloat16 l0 = __float2bfloat16(x0 - __bfloat162float(h0));
    __nv_bfloat16 l1 = __float2bfloat16(x1 - __bfloat162float(h1));
    __nv_bfloat162 hp = {h0, h1}, lp = {l0, l1};
    lo_out = *(uint32_t*)&lp;
    return *(uint32_t*)&hp;
}

// ===================== split-bf16 tensor-core GEMM ==========================
#define APITCH 40
#define BPITCH 136
#define OFF_A_HI 0
#define OFF_A_LO (128*APITCH*2)
#define OFF_B_HI (2*128*APITCH*2)
#define OFF_B_LO (2*128*APITCH*2 + 32*BPITCH*2)
#define STAGE_SZ (2*128*APITCH*2 + 2*32*BPITCH*2)
#define GM_SMEM  (2*STAGE_SZ)

__global__ void __launch_bounds__(256, 1) gemm_mma(
    const float* __restrict__ A, const float* __restrict__ W,
    const float* __restrict__ bias,
    float* __restrict__ C0, float* __restrict__ C1, float* __restrict__ C2,
    int K, int Nmat, long long Wstride, int mode, int relu)
{
    extern __shared__ char smem[];
    const uint32_t sb = smem_u32(smem);
    const int tid = threadIdx.x;
    const int wid = tid >> 5, lid = tid & 31;
    const int wm = wid & 3, wn = wid >> 2;
    const int m0 = wm * 32, n0 = wn * 64;

    const int nbase = blockIdx.x * 128;
    const int mat = nbase / Nmat;
    const int ncol = nbase - mat * Nmat;
    const float* Wp = W + (size_t)mat * (size_t)Wstride + ncol;
    const float* Ap = A + (size_t)blockIdx.y * 128 * (size_t)K;

    float acc[2][8][4];
#pragma unroll
    for (int i = 0; i < 2; i++)
#pragma unroll
        for (int j = 0; j < 8; j++)
#pragma unroll
            for (int r = 0; r < 4; r++) acc[i][j][r] = 0.f;

    const int arow = tid >> 3, ac4 = tid & 7;
    const int brow = tid >> 5, bc4 = tid & 31;

    float4 aR[4], bR[4];
    auto loadG = [&](int t) {
        const int k0 = t * 32;
#pragma unroll
        for (int i = 0; i < 4; i++)
            aR[i] = *(const float4*)(Ap + (size_t)(arow + i * 32) * K + k0 + ac4 * 4);
#pragma unroll
        for (int i = 0; i < 4; i++)
            bR[i] = *(const float4*)(Wp + (size_t)(k0 + brow + i * 8) * Nmat + bc4 * 4);
    };
    auto storeS = [&](int s) {
        char* base = smem + s * STAGE_SZ;
#pragma unroll
        for (int i = 0; i < 4; i++) {
            uint32_t l0, l1, h0, h1;
            h0 = pack_split(aR[i].x, aR[i].y, l0);
            h1 = pack_split(aR[i].z, aR[i].w, l1);
            uint32_t off = ((arow + i * 32) * APITCH + ac4 * 4) * 2;
            *(uint2*)(base + OFF_A_HI + off) = make_uint2(h0, h1);
            *(uint2*)(base + OFF_A_LO + off) = make_uint2(l0, l1);
        }
#pragma unroll
        for (int i = 0; i < 4; i++) {
            uint32_t l0, l1, h0, h1;
            h0 = pack_split(bR[i].x, bR[i].y, l0);
            h1 = pack_split(bR[i].z, bR[i].w, l1);
            uint32_t off = ((brow + i * 8) * BPITCH + bc4 * 4) * 2;
            *(uint2*)(base + OFF_B_HI + off) = make_uint2(h0, h1);
            *(uint2*)(base + OFF_B_LO + off) = make_uint2(l0, l1);
        }
    };

    const int lr = (lid & 7) + ((lid >> 3) & 1) * 8;
    const int lc = (lid >> 4) * 8;

    loadG(0);
    storeS(0);
    __syncthreads();

    const int T = K / 32;
    for (int t = 0; t < T; t++) {
        if (t + 1 < T) loadG(t + 1);
        const uint32_t stg = sb + (t & 1) * STAGE_SZ;
#pragma unroll
        for (int ks = 0; ks < 2; ks++) {
            uint32_t ah[2][4], al[2][4];
#pragma unroll
            for (int mt = 0; mt < 2; mt++) {
                uint32_t aoff = ((m0 + mt * 16 + lr) * APITCH + ks * 16 + lc) * 2;
                ldmA(ah[mt], stg + OFF_A_HI + aoff);
                ldmA(al[mt], stg + OFF_A_LO + aoff);
            }
            uint32_t bh[4][4], bl[4][4];
#pragma unroll
            for (int ng = 0; ng < 4; ng++) {
                uint32_t boff = ((ks * 16 + lr) * BPITCH + n0 + ng * 16 + lc) * 2;
                ldmBT(bh[ng], stg + OFF_B_HI + boff);
                ldmBT(bl[ng], stg + OFF_B_LO + boff);
            }
#pragma unroll
            for (int mt = 0; mt < 2; mt++)
#pragma unroll
                for (int j = 0; j < 8; j++) {
                    const uint32_t* bph = &bh[j >> 1][(j & 1) * 2];
                    const uint32_t* bpl = &bl[j >> 1][(j & 1) * 2];
                    mma16816(acc[mt][j], ah[mt], bph);
                    mma16816(acc[mt][j], ah[mt], bpl);
                    mma16816(acc[mt][j], al[mt], bph);
                }
        }
        if (t + 1 < T) {
            storeS((t + 1) & 1);
            __syncthreads();
        }
    }

    const int g = lid >> 2, tq = lid & 3;
    const int browBase = blockIdx.y * 128 + m0;
#pragma unroll
    for (int mt = 0; mt < 2; mt++) {
#pragma unroll
        for (int j = 0; j < 8; j++) {
            int col = ncol + n0 + j * 8 + tq * 2;
            float b0 = bias[(size_t)mat * Nmat + col];
            float b1 = bias[(size_t)mat * Nmat + col + 1];
#pragma unroll
            for (int h = 0; h < 2; h++) {
                int row = browBase + mt * 16 + g + h * 8;
                float v0 = acc[mt][j][h * 2 + 0] + b0;
                float v1 = acc[mt][j][h * 2 + 1] + b1;
                if (relu) { v0 = fmaxf(v0, 0.f); v1 = fmaxf(v1, 0.f); }
                if (mode == 0) {
                    *(float2*)(C0 + (size_t)row * Nmat + col) = make_float2(v0, v1);
                } else {
                    float* C = (mat == 0) ? C0 : ((mat == 1) ? C1 : C2);
                    int b_ = row >> 9, l_ = row & (Ls - 1);
                    int h_ = col >> 6, dk = col & (DK_ - 1);
                    *(float2*)(C + (((size_t)(b_ * Hh + h_)) * Ls + l_) * DK_ + dk)
                        = make_float2(v0, v1);
                }
            }
        }
    }
}

// ===================== fused flash attention (bf16-split mma) ===============
// grid (4 q-tiles, B*H). 8 warps x 16 rows = 128-row q tile; kv chunks of 64.
#define QP 72
#define FA_Q_HI 0
#define FA_Q_LO 18432
#define FA_K_HI 36864
#define FA_K_LO 46080
#define FA_V_HI 55296
#define FA_V_LO 64512
#define FA_TOTAL 73728

__global__ void __launch_bounds__(256, 1) flash_kernel(
    const float* __restrict__ Q, const float* __restrict__ K,
    const float* __restrict__ V, float* __restrict__ O, int causal)
{
    extern __shared__ char smem[];
    const uint32_t sb = smem_u32(smem);
    const int tid = threadIdx.x, wid = tid >> 5, lid = tid & 31;
    const int qt = blockIdx.x, bh = blockIdx.y;
    const int b_ = bh >> 3, h_ = bh & 7;
    const float* Qp = Q + ((size_t)bh * Ls + qt * 128) * DK_;
    const float* Kp = K + (size_t)bh * Ls * DK_;
    const float* Vp = V + (size_t)bh * Ls * DK_;

    // load Q tile (128 x 64) hi/lo
#pragma unroll
    for (int i = 0; i < 8; i++) {
        int idx = tid + i * 256;
        int row = idx >> 4, c4 = idx & 15;
        float4 v = *(const float4*)(Qp + (size_t)row * DK_ + c4 * 4);
        uint32_t l0, l1, h0, h1;
        h0 = pack_split(v.x, v.y, l0);
        h1 = pack_split(v.z, v.w, l1);
        uint32_t off = (row * QP + c4 * 4) * 2;
        *(uint2*)(smem + FA_Q_HI + off) = make_uint2(h0, h1);
        *(uint2*)(smem + FA_Q_LO + off) = make_uint2(l0, l1);
    }
    __syncthreads();

    const int lr = (lid & 7) + ((lid >> 3) & 1) * 8;
    const int lc = (lid >> 4) * 8;
    const int g = lid >> 2, tq = lid & 3;
    const int m0 = wid * 16;

    // persistent Q fragments
    uint32_t qh[4][4], ql[4][4];
#pragma unroll
    for (int ks = 0; ks < 4; ks++) {
        uint32_t off = ((m0 + lr) * QP + ks * 16 + lc) * 2;
        ldmA(qh[ks], sb + FA_Q_HI + off);
        ldmA(ql[ks], sb + FA_Q_LO + off);
    }

    float acc_o[8][4];
#pragma unroll
    for (int j = 0; j < 8; j++)
#pragma unroll
        for (int r = 0; r < 4; r++) acc_o[j][r] = 0.f;
    float mrow[2] = {-1e30f, -1e30f};
    float lrow[2] = {0.f, 0.f};

    const int nch = causal ? 2 * (qt + 1) : 8;
    for (int kt = 0; kt < nch; kt++) {
        __syncthreads();
        // load K,V chunk (64 x 64 each) hi/lo
#pragma unroll
        for (int i = 0; i < 4; i++) {
            int idx = tid + i * 256;
            int row = idx >> 4, c4 = idx & 15;
            uint32_t off = (row * QP + c4 * 4) * 2;
            float4 kv = *(const float4*)(Kp + (size_t)(kt * 64 + row) * DK_ + c4 * 4);
            uint32_t l0, l1, h0, h1;
            h0 = pack_split(kv.x, kv.y, l0);
            h1 = pack_split(kv.z, kv.w, l1);
            *(uint2*)(smem + FA_K_HI + off) = make_uint2(h0, h1);
            *(uint2*)(smem + FA_K_LO + off) = make_uint2(l0, l1);
            float4 vv = *(const float4*)(Vp + (size_t)(kt * 64 + row) * DK_ + c4 * 4);
            h0 = pack_split(vv.x, vv.y, l0);
            h1 = pack_split(vv.z, vv.w, l1);
            *(uint2*)(smem + FA_V_HI + off) = make_uint2(h0, h1);
            *(uint2*)(smem + FA_V_LO + off) = make_uint2(l0, l1);
        }
        __syncthreads();

        // ---- S = Q K^T ----
        float s[8][4];
#pragma unroll
        for (int j = 0; j < 8; j++)
#pragma unroll
            for (int r = 0; r < 4; r++) s[j][r] = 0.f;
#pragma unroll
        for (int ks = 0; ks < 4; ks++) {
            uint32_t kh[4][4], kl[4][4];
#pragma unroll
            for (int ng = 0; ng < 4; ng++) {
                uint32_t off = ((ng * 16 + lr) * QP + ks * 16 + lc) * 2;
                ldmA(kh[ng], sb + FA_K_HI + off);
                ldmA(kl[ng], sb + FA_K_LO + off);
            }
#pragma unroll
            for (int ng = 0; ng < 4; ng++) {
                uint32_t b0h[2] = {kh[ng][0], kh[ng][2]};
                uint32_t b1h[2] = {kh[ng][1], kh[ng][3]};
                uint32_t b0l[2] = {kl[ng][0], kl[ng][2]};
                uint32_t b1l[2] = {kl[ng][1], kl[ng][3]};
                mma16816(s[ng * 2],     qh[ks], b0h);
                mma16816(s[ng * 2],     ql[ks], b0h);
                mma16816(s[ng * 2],     qh[ks], b0l);
                mma16816(s[ng * 2 + 1], qh[ks], b1h);
                mma16816(s[ng * 2 + 1], ql[ks], b1h);
                mma16816(s[ng * 2 + 1], qh[ks], b1l);
            }
        }

        // ---- online softmax ----
        const bool diag = causal && (kt >= 2 * qt);
#pragma unroll
        for (int r = 0; r < 2; r++) {
            int grow = qt * 128 + m0 + g + r * 8;
            float mx = -1e30f;
#pragma unroll
            for (int j = 0; j < 8; j++) {
                float v0 = s[j][r * 2] * 0.125f;
                float v1 = s[j][r * 2 + 1] * 0.125f;
                if (diag) {
                    int c0 = kt * 64 + j * 8 + tq * 2;
                    if (c0 > grow) v0 = -1e9f;
                    if (c0 + 1 > grow) v1 = -1e9f;
                }
                s[j][r * 2] = v0;
                s[j][r * 2 + 1] = v1;
                mx = fmaxf(mx, fmaxf(v0, v1));
            }
            mx = fmaxf(mx, __shfl_xor_sync(0xffffffffu, mx, 1));
            mx = fmaxf(mx, __shfl_xor_sync(0xffffffffu, mx, 2));
            float mnew = fmaxf(mrow[r], mx);
            float alpha = __expf(mrow[r] - mnew);
            float sum = 0.f;
#pragma unroll
            for (int j = 0; j < 8; j++) {
                float p0 = __expf(s[j][r * 2] - mnew);
                float p1 = __expf(s[j][r * 2 + 1] - mnew);
                s[j][r * 2] = p0;
                s[j][r * 2 + 1] = p1;
                sum += p0 + p1;
            }
            sum += __shfl_xor_sync(0xffffffffu, sum, 1);
            sum += __shfl_xor_sync(0xffffffffu, sum, 2);
            lrow[r] = lrow[r] * alpha + sum;
            mrow[r] = mnew;
#pragma unroll
            for (int j = 0; j < 8; j++) {
                acc_o[j][r * 2] *= alpha;
                acc_o[j][r * 2 + 1] *= alpha;
            }
        }

        // ---- O += P V ----
#pragma unroll
        for (int c = 0; c < 4; c++) {
            uint32_t ph[4], pl[4];
            ph[0] = pack_split(s[2 * c][0],     s[2 * c][1],     pl[0]);
            ph[1] = pack_split(s[2 * c][2],     s[2 * c][3],     pl[1]);
            ph[2] = pack_split(s[2 * c + 1][0], s[2 * c + 1][1], pl[2]);
            ph[3] = pack_split(s[2 * c + 1][2], s[2 * c + 1][3], pl[3]);
            uint32_t vh[4][4], vl[4][4];
#pragma unroll
            for (int ng = 0; ng < 4; ng++) {
                uint32_t off = ((c * 16 + lr) * QP + ng * 16 + lc) * 2;
                ldmBT(vh[ng], sb + FA_V_HI + off);
                ldmBT(vl[ng], sb + FA_V_LO + off);
            }
#pragma unroll
            for (int j = 0; j < 8; j++) {
                uint32_t bh2[2] = {vh[j >> 1][(j & 1) * 2], vh[j >> 1][(j & 1) * 2 + 1]};
                uint32_t bl2[2] = {vl[j >> 1][(j & 1) * 2], vl[j >> 1][(j & 1) * 2 + 1]};
                mma16816(acc_o[j], ph, bh2);
                mma16816(acc_o[j], pl, bh2);
                mma16816(acc_o[j], ph, bl2);
            }
        }
    }

    // ---- write O (scatter to [B, L, D]) ----
#pragma unroll
    for (int r = 0; r < 2; r++) {
        float inv = 1.f / lrow[r];
        int row = qt * 128 + m0 + g + r * 8;
        float* Ob = O + ((size_t)b_ * Ls + row) * Dm + h_ * DK_;
#pragma unroll
        for (int j = 0; j < 8; j++) {
            *(float2*)(Ob + j * 8 + tq * 2)
                = make_float2(acc_o[j][r * 2] * inv, acc_o[j][r * 2 + 1] * inv);
        }
    }
}

// ---------------- positional encoding add ----------------
__global__ void posenc_add(const float* __restrict__ in, float* __restrict__ out) {
    int idx = blockIdx.x * blockDim.x + threadIdx.x;
    if (idx >= Bb * Ls * Dm) return;
    int d = idx & (Dm - 1);
    int l = (idx >> 9) & (Ls - 1);
    int i2 = d & ~1;
    float div = expf(-(float)i2 * (9.210340371976184f / (float)Dm));
    float ang = (float)l * div;
    float pe = (d & 1) ? cosf(ang) : sinf(ang);
    out[idx] = in[idx] + pe;
}

// ---------------- fused residual + LayerNorm ----------------
__global__ void ln_kernel(const float* __restrict__ x, const float* __restrict__ res,
                          const float* __restrict__ g, const float* __restrict__ b,
                          float* __restrict__ out)
{
    __shared__ float r1[256];
    __shared__ float r2[256];
    size_t row = blockIdx.x;
    int tid = threadIdx.x;
    const float* xr = x + row * Dm;
    float v0 = xr[tid], v1 = xr[tid + 256];
    if (res) {
        const float* rr = res + row * Dm;
        v0 += rr[tid];
        v1 += rr[tid + 256];
    }
    r1[tid] = v0 + v1;
    r2[tid] = v0 * v0 + v1 * v1;
    __syncthreads();
    for (int s = 128; s > 0; s >>= 1) {
        if (tid < s) { r1[tid] += r1[tid + s]; r2[tid] += r2[tid + s]; }
        __syncthreads();
    }
    float mu = r1[0] * (1.f / Dm);
    float var = r2[0] * (1.f / Dm) - mu * mu;
    float rs = rsqrtf(var + 1e-5f);
    out[row * Dm + tid]       = (v0 - mu) * rs * g[tid]       + b[tid];
    out[row * Dm + tid + 256] = (v1 - mu) * rs * g[tid + 256] + b[tid + 256];
}

// ---------------- host orchestration ----------------
static inline void run_mma(const float* A, const float* W, const float* bias,
                           float* C0, float* C1, float* C2,
                           int K, int Nmat, long long Wstride, int nTilesX,
                           int mode, int relu)
{
    dim3 grid(nTilesX, MROWS / 128);
    gemm_mma<<<grid, 256, GM_SMEM>>>(A, W, bias, C0, C1, C2, K, Nmat, Wstride, mode, relu);
}

extern "C" void kernel_launch(void* const* d_in, const int* in_sizes, int n_in,
                              void* d_out, int out_size)
{
    static bool attrSet = false;
    if (!attrSet) {
        cudaFuncSetAttribute(gemm_mma, cudaFuncAttributeMaxDynamicSharedMemorySize, GM_SMEM);
        cudaFuncSetAttribute(flash_kernel, cudaFuncAttributeMaxDynamicSharedMemorySize, FA_TOTAL);
        attrSet = true;
    }

    const float* src        = (const float*)d_in[0];
    const float* tgt        = (const float*)d_in[1];
    const float* enc_attn_W = (const float*)d_in[2];
    const float* enc_attn_b = (const float*)d_in[3];
    const float* enc_ffn_W1 = (const float*)d_in[4];
    const float* enc_ffn_b1 = (const float*)d_in[5];
    const float* enc_ffn_W2 = (const float*)d_in[6];
    const float* enc_ffn_b2 = (const float*)d_in[7];
    const float* enc_ln_g   = (const float*)d_in[8];
    const float* enc_ln_b   = (const float*)d_in[9];
    const float* enc_fng    = (const float*)d_in[10];
    const float* enc_fnb    = (const float*)d_in[11];
    const float* dec_sW     = (const float*)d_in[12];
    const float* dec_sb     = (const float*)d_in[13];
    const float* dec_cW     = (const float*)d_in[14];
    const float* dec_cb     = (const float*)d_in[15];
    const float* dW1        = (const float*)d_in[16];
    const float* db1        = (const float*)d_in[17];
    const float* dW2        = (const float*)d_in[18];
    const float* db2        = (const float*)d_in[19];
    const float* dec_ln_g   = (const float*)d_in[20];
    const float* dec_ln_b   = (const float*)d_in[21];
    const float* dec_fng    = (const float*)d_in[22];
    const float* dec_fnb    = (const float*)d_in[23];
    // d_in[24] = tgt_mask: exact causal tril -> applied analytically.

    float *x, *y, *mem, *q, *k, *v, *ctx, *tmp, *h1;
    cudaGetSymbolAddress((void**)&x,   g_x);
    cudaGetSymbolAddress((void**)&y,   g_y);
    cudaGetSymbolAddress((void**)&mem, g_mem);
    cudaGetSymbolAddress((void**)&q,   g_q);
    cudaGetSymbolAddress((void**)&k,   g_k);
    cudaGetSymbolAddress((void**)&v,   g_v);
    cudaGetSymbolAddress((void**)&ctx, g_ctx);
    cudaGetSymbolAddress((void**)&tmp, g_tmp);
    cudaGetSymbolAddress((void**)&h1,  g_h1);

    const long long DD = (long long)Dm * Dm;
    const int nElem = Bb * Ls * Dm;

    // ===== encoder =====
    posenc_add<<<(nElem + 255) / 256, 256>>>(src, x);
    for (int l = 0; l < 4; l++) {
        const float* W  = enc_attn_W + (size_t)l * 4 * DD;
        const float* bb = enc_attn_b + (size_t)l * 4 * Dm;
        run_mma(x, W, bb, q, k, v, Dm, Dm, DD, 12, 1, 0);          // fused QKV
        flash_kernel<<<dim3(4, Bb * Hh), 256, FA_TOTAL>>>(q, k, v, ctx, 0);
        run_mma(ctx, W + 3 * DD, bb + 3 * Dm, tmp, 0, 0, Dm, Dm, 0, 4, 0, 0);
        ln_kernel<<<MROWS, 256>>>(x, tmp, enc_ln_g + (size_t)(l * 2) * Dm,
                                  enc_ln_b + (size_t)(l * 2) * Dm, x);
        run_mma(x, enc_ffn_W1 + (size_t)l * Dm * DFF_, enc_ffn_b1 + (size_t)l * DFF_,
                h1, 0, 0, Dm, DFF_, 0, 16, 0, 1);
        run_mma(h1, enc_ffn_W2 + (size_t)l * DFF_ * Dm, enc_ffn_b2 + (size_t)l * Dm,
                tmp, 0, 0, DFF_, Dm, 0, 4, 0, 0);
        ln_kernel<<<MROWS, 256>>>(x, tmp, enc_ln_g + (size_t)(l * 2 + 1) * Dm,
                                  enc_ln_b + (size_t)(l * 2 + 1) * Dm, x);
    }
    ln_kernel<<<MROWS, 256>>>(x, nullptr, enc_fng, enc_fnb, mem);

    // ===== decoder =====
    posenc_add<<<(nElem + 255) / 256, 256>>>(tgt, y);
    for (int l = 0; l < 4; l++) {
        // masked self-attention
        {
            const float* W  = dec_sW + (size_t)l * 4 * DD;
            const float* bb = dec_sb + (size_t)l * 4 * Dm;
            run_mma(y, W, bb, q, k, v, Dm, Dm, DD, 12, 1, 0);
            flash_kernel<<<dim3(4, Bb * Hh), 256, FA_TOTAL>>>(q, k, v, ctx, 1);
            run_mma(ctx, W + 3 * DD, bb + 3 * Dm, tmp, 0, 0, Dm, Dm, 0, 4, 0, 0);
            ln_kernel<<<MROWS, 256>>>(y, tmp, dec_ln_g + (size_t)(l * 3) * Dm,
                                      dec_ln_b + (size_t)(l * 3) * Dm, y);
        }
        // cross-attention
        {
            const float* W  = dec_cW + (size_t)l * 4 * DD;
            const float* bb = dec_cb + (size_t)l * 4 * Dm;
            run_mma(y,   W,      bb,      q, 0, 0, Dm, Dm, 0, 4, 1, 0);      // Q from y
            run_mma(mem, W + DD, bb + Dm, k, v, 0, Dm, Dm, DD, 8, 1, 0);     // fused K,V
            flash_kernel<<<dim3(4, Bb * Hh), 256, FA_TOTAL>>>(q, k, v, ctx, 0);
            run_mma(ctx, W + 3 * DD, bb + 3 * Dm, tmp, 0, 0, Dm, Dm, 0, 4, 0, 0);
            ln_kernel<<<MROWS, 256>>>(y, tmp, dec_ln_g + (size_t)(l * 3 + 1) * Dm,
                                      dec_ln_b + (size_t)(l * 3 + 1) * Dm, y);
        }
        // FFN
        run_mma(y, dW1 + (size_t)l * Dm * DFF_, db1 + (size_t)l * DFF_,
                h1, 0, 0, Dm, DFF_, 0, 16, 0, 1);
        run_mma(h1, dW2 + (size_t)l * DFF_ * Dm, db2 + (size_t)l * Dm,
                tmp, 0, 0, DFF_, Dm, 0, 4, 0, 0);
        ln_kernel<<<MROWS, 256>>>(y, tmp, dec_ln_g + (size_t)(l * 3 + 2) * Dm,
                                  dec_ln_b + (size_t)(l * 3 + 2) * Dm, y);
    }
    ln_kernel<<<MROWS, 256>>>(y, nullptr, dec_fng, dec_fnb, (float*)d_out);
}

// round 5
// speedup vs baseline: 3.3295x; 1.1331x over previous
#include <cuda_runtime.h>
#include <cuda_bf16.h>
#include <cstdint>
#include <math.h>

typedef __nv_bfloat16 bf16;

// ---------------- problem constants ----------------
#define Bb   8
#define Ls   512
#define Dm   512
#define Hh   8
#define DK_  64
#define DFF_ 2048
#define MROWS (Bb*Ls)   // 4096
#define DD   (Dm*Dm)    // 262144

// ---------------- scratch (device globals; no allocation) ----------------
__device__ float g_x   [MROWS*Dm];
__device__ float g_y   [MROWS*Dm];
__device__ float g_mem [MROWS*Dm];
__device__ float g_tmp [MROWS*Dm];

__device__ bf16 g_xh[MROWS*Dm],  g_xl[MROWS*Dm];
__device__ bf16 g_yh[MROWS*Dm],  g_yl[MROWS*Dm];
__device__ bf16 g_mh[MROWS*Dm],  g_ml[MROWS*Dm];
__device__ bf16 g_qh[MROWS*Dm],  g_ql[MROWS*Dm];
__device__ bf16 g_kh[MROWS*Dm],  g_kl[MROWS*Dm];
__device__ bf16 g_vh[MROWS*Dm],  g_vl[MROWS*Dm];
__device__ bf16 g_ch[MROWS*Dm],  g_cl[MROWS*Dm];
__device__ bf16 g_h1h[(size_t)MROWS*DFF_], g_h1l[(size_t)MROWS*DFF_];

// pre-split weights: [encA | encF1 | encF2 | decS | decC | decF1 | decF2]
#define WOFF_EA  0
#define WOFF_EF1 (WOFF_EA  + 4*4*DD)
#define WOFF_EF2 (WOFF_EF1 + 4*Dm*DFF_)
#define WOFF_DS  (WOFF_EF2 + 4*Dm*DFF_)
#define WOFF_DC  (WOFF_DS  + 4*4*DD)
#define WOFF_DF1 (WOFF_DC  + 4*4*DD)
#define WOFF_DF2 (WOFF_DF1 + 4*Dm*DFF_)
#define WTOTAL   (WOFF_DF2 + 4*Dm*DFF_)
__device__ bf16 g_whi[WTOTAL];
__device__ bf16 g_wlo[WTOTAL];

// ================= helpers =================
__device__ __forceinline__ uint32_t smem_u32(const void* p) {
    uint32_t a;
    asm("{ .reg .u64 t; cvta.to.shared.u64 t, %1; cvt.u32.u64 %0, t; }" : "=r"(a) : "l"(p));
    return a;
}
__device__ __forceinline__ void ldmA(uint32_t* f, uint32_t addr) {
    asm volatile("ldmatrix.sync.aligned.m8n8.x4.shared.b16 {%0,%1,%2,%3}, [%4];"
                 : "=r"(f[0]), "=r"(f[1]), "=r"(f[2]), "=r"(f[3]) : "r"(addr));
}
__device__ __forceinline__ void ldmBT(uint32_t* f, uint32_t addr) {
    asm volatile("ldmatrix.sync.aligned.m8n8.x4.trans.shared.b16 {%0,%1,%2,%3}, [%4];"
                 : "=r"(f[0]), "=r"(f[1]), "=r"(f[2]), "=r"(f[3]) : "r"(addr));
}
__device__ __forceinline__ void mma16816(float* c, const uint32_t* a, const uint32_t* b) {
    asm volatile("mma.sync.aligned.m16n8k16.row.col.f32.bf16.bf16.f32 "
                 "{%0,%1,%2,%3}, {%4,%5,%6,%7}, {%8,%9}, {%0,%1,%2,%3};"
                 : "+f"(c[0]), "+f"(c[1]), "+f"(c[2]), "+f"(c[3])
                 : "r"(a[0]), "r"(a[1]), "r"(a[2]), "r"(a[3]), "r"(b[0]), "r"(b[1]));
}
__device__ __forceinline__ uint32_t pack_split(float x0, float x1, uint32_t& lo_out) {
    bf16 h0 = __float2bfloat16(x0);
    bf16 h1 = __float2bfloat16(x1);
    bf16 l0 = __float2bfloat16(x0 - __bfloat162float(h0));
    bf16 l1 = __float2bfloat16(x1 - __bfloat162float(h1));
    __nv_bfloat162 hp = {h0, h1}, lp = {l0, l1};
    lo_out = *(uint32_t*)&lp;
    return *(uint32_t*)&hp;
}
__device__ __forceinline__ void cpa16(uint32_t saddr, const void* gaddr) {
    asm volatile("cp.async.ca.shared.global [%0], [%1], 16;" :: "r"(saddr), "l"(gaddr));
}
#define CP_COMMIT() asm volatile("cp.async.commit_group;" ::: "memory")
#define CP_WAIT1()  asm volatile("cp.async.wait_group 1;"  ::: "memory")

// ---------------- weight split kernel ----------------
__global__ void wsplit(const float* __restrict__ in, bf16* __restrict__ hi,
                       bf16* __restrict__ lo, int n4)
{
    int i = blockIdx.x * blockDim.x + threadIdx.x;
    if (i >= n4) return;
    float4 v = ((const float4*)in)[i];
    uint32_t l0, l1;
    uint32_t h0 = pack_split(v.x, v.y, l0);
    uint32_t h1 = pack_split(v.z, v.w, l1);
    ((uint2*)hi)[i] = make_uint2(h0, h1);
    ((uint2*)lo)[i] = make_uint2(l0, l1);
}

// ===================== cp.async bf16 tensor-core GEMM =======================
// smem stage layout (bytes): A 128x32 bf16 pitch 80B; B 32x128 bf16 pitch 272B
#define OFF_A_HI 0
#define OFF_A_LO 10240
#define OFF_B_HI 20480
#define OFF_B_LO 29184
#define STAGE_SZ 37888
#define NSTAGE 3
#define GM_SMEM (NSTAGE*STAGE_SZ)   // 113664

// mode 0: f32 row-major to Cf.  mode 1: bf16 hi/lo head-scatter to (Ch,Cl)[mat].
// mode 2: bf16 hi/lo row-major to Ch0/Cl0.
__global__ void __launch_bounds__(256, 2) gemm_bf(
    const bf16* __restrict__ Ahi, const bf16* __restrict__ Alo,
    const bf16* __restrict__ Whi, const bf16* __restrict__ Wlo,
    const float* __restrict__ bias, float* __restrict__ Cf,
    bf16* __restrict__ Ch0, bf16* __restrict__ Cl0,
    bf16* __restrict__ Ch1, bf16* __restrict__ Cl1,
    bf16* __restrict__ Ch2, bf16* __restrict__ Cl2,
    int K, int Nmat, long long Wstride, int mode, int relu)
{
    extern __shared__ char smem[];
    const uint32_t sb = smem_u32(smem);
    const int tid = threadIdx.x;
    const int wid = tid >> 5, lid = tid & 31;
    const int wm = wid & 3, wn = wid >> 2;
    const int m0 = wm * 32, n0 = wn * 64;

    const int nbase = blockIdx.x * 128;
    const int mat = nbase / Nmat;
    const int ncol = nbase - mat * Nmat;
    const bf16* Wph = Whi + (size_t)mat * (size_t)Wstride + ncol;
    const bf16* Wpl = Wlo + (size_t)mat * (size_t)Wstride + ncol;
    const bf16* Aph = Ahi + (size_t)blockIdx.y * 128 * (size_t)K;
    const bf16* Apl = Alo + (size_t)blockIdx.y * 128 * (size_t)K;

    float acc[2][8][4];
#pragma unroll
    for (int i = 0; i < 2; i++)
#pragma unroll
        for (int j = 0; j < 8; j++)
#pragma unroll
            for (int r = 0; r < 4; r++) acc[i][j][r] = 0.f;

    auto loadS = [&](int t) {
        const int k0 = t * 32;
        const uint32_t sbase = sb + (t % NSTAGE) * STAGE_SZ;
        // A: 128 rows x 4 chunks of 16B
#pragma unroll
        for (int i = 0; i < 2; i++) {
            int idx = tid + i * 256;
            int row = idx >> 2, ch = idx & 3;
            size_t go = (size_t)row * K + k0 + ch * 8;
            uint32_t so = row * 80 + ch * 16;
            cpa16(sbase + OFF_A_HI + so, Aph + go);
            cpa16(sbase + OFF_A_LO + so, Apl + go);
        }
        // B: 32 rows x 16 chunks of 16B
#pragma unroll
        for (int i = 0; i < 2; i++) {
            int idx = tid + i * 256;
            int row = idx >> 4, ch = idx & 15;
            size_t go = (size_t)(k0 + row) * Nmat + ch * 8;
            uint32_t so = row * 272 + ch * 16;
            cpa16(sbase + OFF_B_HI + so, Wph + go);
            cpa16(sbase + OFF_B_LO + so, Wpl + go);
        }
        CP_COMMIT();
    };

    const int T = K / 32;
    loadS(0);
    loadS(1);

    const int lr = (lid & 7) + ((lid >> 3) & 1) * 8;
    const int lc = (lid >> 4) * 8;

    for (int t = 0; t < T; t++) {
        CP_WAIT1();
        __syncthreads();
        const uint32_t stg = sb + (t % NSTAGE) * STAGE_SZ;
#pragma unroll
        for (int ks = 0; ks < 2; ks++) {
            uint32_t ah[2][4], al[2][4];
#pragma unroll
            for (int mt = 0; mt < 2; mt++) {
                uint32_t aoff = ((m0 + mt * 16 + lr) * 40 + ks * 16 + lc) * 2;
                ldmA(ah[mt], stg + OFF_A_HI + aoff);
                ldmA(al[mt], stg + OFF_A_LO + aoff);
            }
#pragma unroll
            for (int ng = 0; ng < 4; ng++) {
                uint32_t bh4[4], bl4[4];
                uint32_t boff = ((ks * 16 + lr) * 136 + n0 + ng * 16 + lc) * 2;
                ldmBT(bh4, stg + OFF_B_HI + boff);
                ldmBT(bl4, stg + OFF_B_LO + boff);
#pragma unroll
                for (int mt = 0; mt < 2; mt++)
#pragma unroll
                    for (int jj = 0; jj < 2; jj++) {
                        float* c = acc[mt][ng * 2 + jj];
                        mma16816(c, ah[mt], &bh4[jj * 2]);
                        mma16816(c, ah[mt], &bl4[jj * 2]);
                        mma16816(c, al[mt], &bh4[jj * 2]);
                    }
            }
        }
        if (t + 2 < T) loadS(t + 2); else CP_COMMIT();
    }

    // ---- epilogue ----
    const int g = lid >> 2, tq = lid & 3;
    const int browBase = blockIdx.y * 128 + m0;
    bf16* Chm = (mat == 0) ? Ch0 : ((mat == 1) ? Ch1 : Ch2);
    bf16* Clm = (mat == 0) ? Cl0 : ((mat == 1) ? Cl1 : Cl2);
#pragma unroll
    for (int mt = 0; mt < 2; mt++) {
#pragma unroll
        for (int j = 0; j < 8; j++) {
            int col = ncol + n0 + j * 8 + tq * 2;
            float b0 = bias[(size_t)mat * Nmat + col];
            float b1 = bias[(size_t)mat * Nmat + col + 1];
#pragma unroll
            for (int h = 0; h < 2; h++) {
                int row = browBase + mt * 16 + g + h * 8;
                float v0 = acc[mt][j][h * 2 + 0] + b0;
                float v1 = acc[mt][j][h * 2 + 1] + b1;
                if (relu) { v0 = fmaxf(v0, 0.f); v1 = fmaxf(v1, 0.f); }
                if (mode == 0) {
                    *(float2*)(Cf + (size_t)row * Nmat + col) = make_float2(v0, v1);
                } else {
                    uint32_t lo, hi = pack_split(v0, v1, lo);
                    size_t off;
                    if (mode == 2) {
                        off = (size_t)row * Nmat + col;
                    } else {
                        int b_ = row >> 9, l_ = row & (Ls - 1);
                        int h_ = col >> 6, dk = col & (DK_ - 1);
                        off = (((size_t)(b_ * Hh + h_)) * Ls + l_) * DK_ + dk;
                    }
                    *(uint32_t*)(Chm + off) = hi;
                    *(uint32_t*)(Clm + off) = lo;
                }
            }
        }
    }
}

// ===================== fused flash attention (bf16 in/out) ==================
#define QP 72
#define FA_Q_HI 0
#define FA_Q_LO 18432
#define FA_K_HI 36864
#define FA_K_LO 46080
#define FA_V_HI 55296
#define FA_V_LO 64512
#define FA_TOTAL 73728

__global__ void __launch_bounds__(256, 1) flash_kernel(
    const bf16* __restrict__ Qh, const bf16* __restrict__ Ql,
    const bf16* __restrict__ Kh, const bf16* __restrict__ Kl,
    const bf16* __restrict__ Vh, const bf16* __restrict__ Vl,
    bf16* __restrict__ Oh, bf16* __restrict__ Ol, int causal)
{
    extern __shared__ char smem[];
    const uint32_t sb = smem_u32(smem);
    const int tid = threadIdx.x, wid = tid >> 5, lid = tid & 31;
    const int qt = blockIdx.x, bh = blockIdx.y;
    const int b_ = bh >> 3, h_ = bh & 7;
    const bf16* Qph = Qh + ((size_t)bh * Ls + qt * 128) * DK_;
    const bf16* Qpl = Ql + ((size_t)bh * Ls + qt * 128) * DK_;
    const bf16* Kph = Kh + (size_t)bh * Ls * DK_;
    const bf16* Kpl = Kl + (size_t)bh * Ls * DK_;
    const bf16* Vph = Vh + (size_t)bh * Ls * DK_;
    const bf16* Vpl = Vl + (size_t)bh * Ls * DK_;

    // load Q tile (128 x 64 bf16), 8 chunks of 16B per row
#pragma unroll
    for (int i = 0; i < 4; i++) {
        int idx = tid + i * 256;
        int row = idx >> 3, ch = idx & 7;
        size_t go = (size_t)row * DK_ + ch * 8;
        uint32_t so = row * 144 + ch * 16;
        *(uint4*)(smem + FA_Q_HI + so) = *(const uint4*)(Qph + go);
        *(uint4*)(smem + FA_Q_LO + so) = *(const uint4*)(Qpl + go);
    }
    __syncthreads();

    const int lr = (lid & 7) + ((lid >> 3) & 1) * 8;
    const int lc = (lid >> 4) * 8;
    const int g = lid >> 2, tq = lid & 3;
    const int m0 = wid * 16;

    uint32_t qh[4][4], ql[4][4];
#pragma unroll
    for (int ks = 0; ks < 4; ks++) {
        uint32_t off = ((m0 + lr) * QP + ks * 16 + lc) * 2;
        ldmA(qh[ks], sb + FA_Q_HI + off);
        ldmA(ql[ks], sb + FA_Q_LO + off);
    }

    float acc_o[8][4];
#pragma unroll
    for (int j = 0; j < 8; j++)
#pragma unroll
        for (int r = 0; r < 4; r++) acc_o[j][r] = 0.f;
    float mrow[2] = {-1e30f, -1e30f};
    float lrow[2] = {0.f, 0.f};

    const int nch = causal ? 2 * (qt + 1) : 8;
    for (int kt = 0; kt < nch; kt++) {
        __syncthreads();
#pragma unroll
        for (int i = 0; i < 2; i++) {
            int idx = tid + i * 256;
            int row = idx >> 3, ch = idx & 7;
            size_t go = (size_t)(kt * 64 + row) * DK_ + ch * 8;
            uint32_t so = row * 144 + ch * 16;
            *(uint4*)(smem + FA_K_HI + so) = *(const uint4*)(Kph + go);
            *(uint4*)(smem + FA_K_LO + so) = *(const uint4*)(Kpl + go);
            *(uint4*)(smem + FA_V_HI + so) = *(const uint4*)(Vph + go);
            *(uint4*)(smem + FA_V_LO + so) = *(const uint4*)(Vpl + go);
        }
        __syncthreads();

        // ---- S = Q K^T ----
        float s[8][4];
#pragma unroll
        for (int j = 0; j < 8; j++)
#pragma unroll
            for (int r = 0; r < 4; r++) s[j][r] = 0.f;
#pragma unroll
        for (int ks = 0; ks < 4; ks++) {
#pragma unroll
            for (int ng = 0; ng < 4; ng++) {
                uint32_t kh4[4], kl4[4];
                uint32_t off = ((ng * 16 + lr) * QP + ks * 16 + lc) * 2;
                ldmA(kh4, sb + FA_K_HI + off);
                ldmA(kl4, sb + FA_K_LO + off);
                uint32_t b0h[2] = {kh4[0], kh4[2]};
                uint32_t b1h[2] = {kh4[1], kh4[3]};
                uint32_t b0l[2] = {kl4[0], kl4[2]};
                uint32_t b1l[2] = {kl4[1], kl4[3]};
                mma16816(s[ng * 2],     qh[ks], b0h);
                mma16816(s[ng * 2],     ql[ks], b0h);
                mma16816(s[ng * 2],     qh[ks], b0l);
                mma16816(s[ng * 2 + 1], qh[ks], b1h);
                mma16816(s[ng * 2 + 1], ql[ks], b1h);
                mma16816(s[ng * 2 + 1], qh[ks], b1l);
            }
        }

        // ---- online softmax ----
        const bool diag = causal && (kt >= 2 * qt);
#pragma unroll
        for (int r = 0; r < 2; r++) {
            int grow = qt * 128 + m0 + g + r * 8;
            float mx = -1e30f;
#pragma unroll
            for (int j = 0; j < 8; j++) {
                float v0 = s[j][r * 2] * 0.125f;
                float v1 = s[j][r * 2 + 1] * 0.125f;
                if (diag) {
                    int c0 = kt * 64 + j * 8 + tq * 2;
                    if (c0 > grow) v0 = -1e9f;
                    if (c0 + 1 > grow) v1 = -1e9f;
                }
                s[j][r * 2] = v0;
                s[j][r * 2 + 1] = v1;
                mx = fmaxf(mx, fmaxf(v0, v1));
            }
            mx = fmaxf(mx, __shfl_xor_sync(0xffffffffu, mx, 1));
            mx = fmaxf(mx, __shfl_xor_sync(0xffffffffu, mx, 2));
            float mnew = fmaxf(mrow[r], mx);
            float alpha = __expf(mrow[r] - mnew);
            float sum = 0.f;
#pragma unroll
            for (int j = 0; j < 8; j++) {
                float p0 = __expf(s[j][r * 2] - mnew);
                float p1 = __expf(s[j][r * 2 + 1] - mnew);
                s[j][r * 2] = p0;
                s[j][r * 2 + 1] = p1;
                sum += p0 + p1;
            }
            sum += __shfl_xor_sync(0xffffffffu, sum, 1);
            sum += __shfl_xor_sync(0xffffffffu, sum, 2);
            lrow[r] = lrow[r] * alpha + sum;
            mrow[r] = mnew;
#pragma unroll
            for (int j = 0; j < 8; j++) {
                acc_o[j][r * 2] *= alpha;
                acc_o[j][r * 2 + 1] *= alpha;
            }
        }

        // ---- O += P V ----
#pragma unroll
        for (int c = 0; c < 4; c++) {
            uint32_t ph[4], pl[4];
            ph[0] = pack_split(s[2 * c][0],     s[2 * c][1],     pl[0]);
            ph[1] = pack_split(s[2 * c][2],     s[2 * c][3],     pl[1]);
            ph[2] = pack_split(s[2 * c + 1][0], s[2 * c + 1][1], pl[2]);
            ph[3] = pack_split(s[2 * c + 1][2], s[2 * c + 1][3], pl[3]);
#pragma unroll
            for (int ng = 0; ng < 4; ng++) {
                uint32_t vh4[4], vl4[4];
                uint32_t off = ((c * 16 + lr) * QP + ng * 16 + lc) * 2;
                ldmBT(vh4, sb + FA_V_HI + off);
                ldmBT(vl4, sb + FA_V_LO + off);
#pragma unroll
                for (int jj = 0; jj < 2; jj++) {
                    float* cacc = acc_o[ng * 2 + jj];
                    mma16816(cacc, ph, &vh4[jj * 2]);
                    mma16816(cacc, pl, &vh4[jj * 2]);
                    mma16816(cacc, ph, &vl4[jj * 2]);
                }
            }
        }
    }

    // ---- write O hi/lo (scatter to [B, L, D]) ----
#pragma unroll
    for (int r = 0; r < 2; r++) {
        float inv = 1.f / lrow[r];
        int row = qt * 128 + m0 + g + r * 8;
        size_t base = ((size_t)b_ * Ls + row) * Dm + h_ * DK_;
#pragma unroll
        for (int j = 0; j < 8; j++) {
            uint32_t lo, hi = pack_split(acc_o[j][r * 2] * inv, acc_o[j][r * 2 + 1] * inv, lo);
            *(uint32_t*)(Oh + base + j * 8 + tq * 2) = hi;
            *(uint32_t*)(Ol + base + j * 8 + tq * 2) = lo;
        }
    }
}

// ---------------- positional encoding add (f32 + hi/lo) ----------------
__global__ void posenc_add(const float* __restrict__ in, float* __restrict__ out,
                           bf16* __restrict__ oh, bf16* __restrict__ ol)
{
    int p = blockIdx.x * blockDim.x + threadIdx.x;
    if (p >= Bb * Ls * Dm / 2) return;
    int d2 = p & (Dm / 2 - 1);
    int l = (p >> 8) & (Ls - 1);
    float div = expf(-(float)(2 * d2) * (9.210340371976184f / (float)Dm));
    float ang = (float)l * div;
    float v0 = in[2 * p] + __sinf(ang);
    float v1 = in[2 * p + 1] + __cosf(ang);
    *(float2*)(out + 2 * p) = make_float2(v0, v1);
    uint32_t lo, hi = pack_split(v0, v1, lo);
    *(uint32_t*)(oh + 2 * p) = hi;
    *(uint32_t*)(ol + 2 * p) = lo;
}

// ---------------- fused residual + LayerNorm (f32 + hi/lo out) -------------
__global__ void ln_kernel(const float* __restrict__ x, const float* __restrict__ res,
                          const float* __restrict__ g, const float* __restrict__ b,
                          float* __restrict__ outf, bf16* __restrict__ oh,
                          bf16* __restrict__ ol)
{
    __shared__ float ss[4], qq[4];
    size_t row = blockIdx.x;
    int tid = threadIdx.x;            // 128 threads
    int wid = tid >> 5, lane = tid & 31;
    float4 v = ((const float4*)(x + row * Dm))[tid];
    if (res) {
        float4 r = ((const float4*)(res + row * Dm))[tid];
        v.x += r.x; v.y += r.y; v.z += r.z; v.w += r.w;
    }
    float s = v.x + v.y + v.z + v.w;
    float q = v.x * v.x + v.y * v.y + v.z * v.z + v.w * v.w;
#pragma unroll
    for (int o = 16; o > 0; o >>= 1) {
        s += __shfl_xor_sync(0xffffffffu, s, o);
        q += __shfl_xor_sync(0xffffffffu, q, o);
    }
    if (lane == 0) { ss[wid] = s; qq[wid] = q; }
    __syncthreads();
    s = ss[0] + ss[1] + ss[2] + ss[3];
    q = qq[0] + qq[1] + qq[2] + qq[3];
    float mu = s * (1.f / Dm);
    float var = q * (1.f / Dm) - mu * mu;
    float rs = rsqrtf(var + 1e-5f);
    float4 gv = ((const float4*)g)[tid];
    float4 bv = ((const float4*)b)[tid];
    float4 o;
    o.x = (v.x - mu) * rs * gv.x + bv.x;
    o.y = (v.y - mu) * rs * gv.y + bv.y;
    o.z = (v.z - mu) * rs * gv.z + bv.z;
    o.w = (v.w - mu) * rs * gv.w + bv.w;
    ((float4*)(outf + row * Dm))[tid] = o;
    if (oh) {
        uint32_t l0, l1;
        uint32_t h0 = pack_split(o.x, o.y, l0);
        uint32_t h1 = pack_split(o.z, o.w, l1);
        *(uint2*)(oh + row * Dm + tid * 4) = make_uint2(h0, h1);
        *(uint2*)(ol + row * Dm + tid * 4) = make_uint2(l0, l1);
    }
}

// ---------------- host orchestration ----------------
static inline void run_gemm(const bf16* Ah, const bf16* Al,
                            const bf16* Wh, const bf16* Wl, const float* bias,
                            float* Cf, bf16* Ch0, bf16* Cl0, bf16* Ch1, bf16* Cl1,
                            bf16* Ch2, bf16* Cl2,
                            int K, int Nmat, long long Wstride, int nTilesX,
                            int mode, int relu)
{
    dim3 grid(nTilesX, MROWS / 128);
    gemm_bf<<<grid, 256, GM_SMEM>>>(Ah, Al, Wh, Wl, bias, Cf,
                                    Ch0, Cl0, Ch1, Cl1, Ch2, Cl2,
                                    K, Nmat, Wstride, mode, relu);
}

extern "C" void kernel_launch(void* const* d_in, const int* in_sizes, int n_in,
                              void* d_out, int out_size)
{
    static bool attrSet = false;
    if (!attrSet) {
        cudaFuncSetAttribute(gemm_bf, cudaFuncAttributeMaxDynamicSharedMemorySize, GM_SMEM);
        cudaFuncSetAttribute(flash_kernel, cudaFuncAttributeMaxDynamicSharedMemorySize, FA_TOTAL);
        attrSet = true;
    }

    const float* src        = (const float*)d_in[0];
    const float* tgt        = (const float*)d_in[1];
    const float* enc_attn_W = (const float*)d_in[2];
    const float* enc_attn_b = (const float*)d_in[3];
    const float* enc_ffn_W1 = (const float*)d_in[4];
    const float* enc_ffn_b1 = (const float*)d_in[5];
    const float* enc_ffn_W2 = (const float*)d_in[6];
    const float* enc_ffn_b2 = (const float*)d_in[7];
    const float* enc_ln_g   = (const float*)d_in[8];
    const float* enc_ln_b   = (const float*)d_in[9];
    const float* enc_fng    = (const float*)d_in[10];
    const float* enc_fnb    = (const float*)d_in[11];
    const float* dec_sW     = (const float*)d_in[12];
    const float* dec_sb     = (const float*)d_in[13];
    const float* dec_cW     = (const float*)d_in[14];
    const float* dec_cb     = (const float*)d_in[15];
    const float* dW1        = (const float*)d_in[16];
    const float* db1        = (const float*)d_in[17];
    const float* dW2        = (const float*)d_in[18];
    const float* db2        = (const float*)d_in[19];
    const float* dec_ln_g   = (const float*)d_in[20];
    const float* dec_ln_b   = (const float*)d_in[21];
    const float* dec_fng    = (const float*)d_in[22];
    const float* dec_fnb    = (const float*)d_in[23];
    // d_in[24] = tgt_mask: exact causal tril -> applied analytically.

    float *x, *y, *mem, *tmp;
    cudaGetSymbolAddress((void**)&x,   g_x);
    cudaGetSymbolAddress((void**)&y,   g_y);
    cudaGetSymbolAddress((void**)&mem, g_mem);
    cudaGetSymbolAddress((void**)&tmp, g_tmp);
    bf16 *xh,*xl,*yh,*yl,*mh,*ml,*qh,*ql,*kh,*kl,*vh,*vl,*ch,*cl,*h1h,*h1l,*whi,*wlo;
    cudaGetSymbolAddress((void**)&xh, g_xh);  cudaGetSymbolAddress((void**)&xl, g_xl);
    cudaGetSymbolAddress((void**)&yh, g_yh);  cudaGetSymbolAddress((void**)&yl, g_yl);
    cudaGetSymbolAddress((void**)&mh, g_mh);  cudaGetSymbolAddress((void**)&ml, g_ml);
    cudaGetSymbolAddress((void**)&qh, g_qh);  cudaGetSymbolAddress((void**)&ql, g_ql);
    cudaGetSymbolAddress((void**)&kh, g_kh);  cudaGetSymbolAddress((void**)&kl, g_kl);
    cudaGetSymbolAddress((void**)&vh, g_vh);  cudaGetSymbolAddress((void**)&vl, g_vl);
    cudaGetSymbolAddress((void**)&ch, g_ch);  cudaGetSymbolAddress((void**)&cl, g_cl);
    cudaGetSymbolAddress((void**)&h1h, g_h1h); cudaGetSymbolAddress((void**)&h1l, g_h1l);
    cudaGetSymbolAddress((void**)&whi, g_whi); cudaGetSymbolAddress((void**)&wlo, g_wlo);

    // ---- pre-split all weights into bf16 hi/lo ----
    const int N4 = 4 * 4 * DD / 4;   // 1048576 float4s per 4M-element group
    wsplit<<<N4 / 256, 256>>>(enc_attn_W, whi + WOFF_EA,  wlo + WOFF_EA,  N4);
    wsplit<<<N4 / 256, 256>>>(enc_ffn_W1, whi + WOFF_EF1, wlo + WOFF_EF1, N4);
    wsplit<<<N4 / 256, 256>>>(enc_ffn_W2, whi + WOFF_EF2, wlo + WOFF_EF2, N4);
    wsplit<<<N4 / 256, 256>>>(dec_sW,     whi + WOFF_DS,  wlo + WOFF_DS,  N4);
    wsplit<<<N4 / 256, 256>>>(dec_cW,     whi + WOFF_DC,  wlo + WOFF_DC,  N4);
    wsplit<<<N4 / 256, 256>>>(dW1,        whi + WOFF_DF1, wlo + WOFF_DF1, N4);
    wsplit<<<N4 / 256, 256>>>(dW2,        whi + WOFF_DF2, wlo + WOFF_DF2, N4);

    const long long DDll = (long long)DD;
    const int nPair = Bb * Ls * Dm / 2;

    // ===== encoder =====
    posenc_add<<<nPair / 256, 256>>>(src, x, xh, xl);
    for (int l = 0; l < 4; l++) {
        const bf16* Wh = whi + WOFF_EA + (size_t)l * 4 * DD;
        const bf16* Wl = wlo + WOFF_EA + (size_t)l * 4 * DD;
        const float* bb = enc_attn_b + (size_t)l * 4 * Dm;
        run_gemm(xh, xl, Wh, Wl, bb, 0, qh, ql, kh, kl, vh, vl,
                 Dm, Dm, DDll, 12, 1, 0);
        flash_kernel<<<dim3(4, Bb * Hh), 256, FA_TOTAL>>>(qh, ql, kh, kl, vh, vl, ch, cl, 0);
        run_gemm(ch, cl, Wh + 3 * DD, Wl + 3 * DD, bb + 3 * Dm, tmp,
                 0, 0, 0, 0, 0, 0, Dm, Dm, 0, 4, 0, 0);
        ln_kernel<<<MROWS, 128>>>(x, tmp, enc_ln_g + (size_t)(l * 2) * Dm,
                                  enc_ln_b + (size_t)(l * 2) * Dm, x, xh, xl);
        run_gemm(xh, xl, whi + WOFF_EF1 + (size_t)l * Dm * DFF_,
                 wlo + WOFF_EF1 + (size_t)l * Dm * DFF_, enc_ffn_b1 + (size_t)l * DFF_,
                 0, h1h, h1l, 0, 0, 0, 0, Dm, DFF_, 0, 16, 2, 1);
        run_gemm(h1h, h1l, whi + WOFF_EF2 + (size_t)l * DFF_ * Dm,
                 wlo + WOFF_EF2 + (size_t)l * DFF_ * Dm, enc_ffn_b2 + (size_t)l * Dm,
                 tmp, 0, 0, 0, 0, 0, 0, DFF_, Dm, 0, 4, 0, 0);
        ln_kernel<<<MROWS, 128>>>(x, tmp, enc_ln_g + (size_t)(l * 2 + 1) * Dm,
                                  enc_ln_b + (size_t)(l * 2 + 1) * Dm, x, xh, xl);
    }
    ln_kernel<<<MROWS, 128>>>(x, nullptr, enc_fng, enc_fnb, mem, mh, ml);

    // ===== decoder =====
    posenc_add<<<nPair / 256, 256>>>(tgt, y, yh, yl);
    for (int l = 0; l < 4; l++) {
        // masked self-attention
        {
            const bf16* Wh = whi + WOFF_DS + (size_t)l * 4 * DD;
            const bf16* Wl = wlo + WOFF_DS + (size_t)l * 4 * DD;
            const float* bb = dec_sb + (size_t)l * 4 * Dm;
            run_gemm(yh, yl, Wh, Wl, bb, 0, qh, ql, kh, kl, vh, vl,
                     Dm, Dm, DDll, 12, 1, 0);
            flash_kernel<<<dim3(4, Bb * Hh), 256, FA_TOTAL>>>(qh, ql, kh, kl, vh, vl, ch, cl, 1);
            run_gemm(ch, cl, Wh + 3 * DD, Wl + 3 * DD, bb + 3 * Dm, tmp,
                     0, 0, 0, 0, 0, 0, Dm, Dm, 0, 4, 0, 0);
            ln_kernel<<<MROWS, 128>>>(y, tmp, dec_ln_g + (size_t)(l * 3) * Dm,
                                      dec_ln_b + (size_t)(l * 3) * Dm, y, yh, yl);
        }
        // cross-attention
        {
            const bf16* Wh = whi + WOFF_DC + (size_t)l * 4 * DD;
            const bf16* Wl = wlo + WOFF_DC + (size_t)l * 4 * DD;
            const float* bb = dec_cb + (size_t)l * 4 * Dm;
            run_gemm(yh, yl, Wh, Wl, bb, 0, qh, ql, 0, 0, 0, 0,
                     Dm, Dm, 0, 4, 1, 0);                                // Q from y
            run_gemm(mh, ml, Wh + DD, Wl + DD, bb + Dm, 0, kh, kl, vh, vl, 0, 0,
                     Dm, Dm, DDll, 8, 1, 0);                             // fused K,V
            flash_kernel<<<dim3(4, Bb * Hh), 256, FA_TOTAL>>>(qh, ql, kh, kl, vh, vl, ch, cl, 0);
            run_gemm(ch, cl, Wh + 3 * DD, Wl + 3 * DD, bb + 3 * Dm, tmp,
                     0, 0, 0, 0, 0, 0, Dm, Dm, 0, 4, 0, 0);
            ln_kernel<<<MROWS, 128>>>(y, tmp, dec_ln_g + (size_t)(l * 3 + 1) * Dm,
                                      dec_ln_b + (size_t)(l * 3 + 1) * Dm, y, yh, yl);
        }
        // FFN
        run_gemm(yh, yl, whi + WOFF_DF1 + (size_t)l * Dm * DFF_,
                 wlo + WOFF_DF1 + (size_t)l * Dm * DFF_, db1 + (size_t)l * DFF_,
                 0, h1h, h1l, 0, 0, 0, 0, Dm, DFF_, 0, 16, 2, 1);
        run_gemm(h1h, h1l, whi + WOFF_DF2 + (size_t)l * DFF_ * Dm,
                 wlo + WOFF_DF2 + (size_t)l * DFF_ * Dm, db2 + (size_t)l * Dm,
                 tmp, 0, 0, 0, 0, 0, 0, DFF_, Dm, 0, 4, 0, 0);
        ln_kernel<<<MROWS, 128>>>(y, tmp, dec_ln_g + (size_t)(l * 3 + 2) * Dm,
                                  dec_ln_b + (size_t)(l * 3 + 2) * Dm, y, yh, yl);
    }
    ln_kernel<<<MROWS, 128>>>(y, nullptr, dec_fng, dec_fnb, (float*)d_out, 0, 0);
}